// round 1
// baseline (speedup 1.0000x reference)
#include <cuda_runtime.h>
#include <math.h>

// Problem constants
#define NV   20000
#define ME   5000
#define EI   160000
#define CDIM 1024
#define HIDD 512

// ---------------- device scratch (static, no allocation) ----------------
__device__ float g_bufA[(size_t)NV * HIDD];   // H1p = X@Wt0^T+bt0 ; later AB for h
__device__ float g_bufB[(size_t)NV * HIDD];   // H1 (after e2v + elu)
__device__ float g_bufC[(size_t)NV * CDIM];   // H2p = H1@Wt1^T+bt1
__device__ float g_bufD[(size_t)NV * CDIM];   // h (layer2 output)
__device__ float g_Y[(size_t)ME * CDIM];      // per-edge means (layer-sized)
__device__ float g_ybuf[(size_t)ME * CDIM];   // y = v2e_mean(h)
__device__ float g_ABy[(size_t)ME * HIDD];    // AB for y attention
__device__ float g_alpha[ME];
__device__ float g_vm[NV];
__device__ float g_vwinv[NV];
__device__ float g_logits[NV];

__device__ int g_degE[ME], g_eoff[ME + 1], g_ecur[ME];
__device__ int g_degV[NV], g_voff[NV + 1], g_vcur[NV];
__device__ int g_elist[EI];   // edge -> vertices
__device__ int g_vlist[EI];   // vertex -> edges

__device__ float g_Wab[512 * 1024];           // [Wa;Wb] combined
__device__ float g_gvec[CDIM];
__device__ float g_gout[CDIM];
__device__ float g_gcat[6 * CDIM];
__device__ float g_gcatn[6 * CDIM];
__device__ unsigned g_menc;
__device__ float g_S;

// ---------------- helpers ----------------
__device__ __forceinline__ unsigned fenc(float f) {
    unsigned u = __float_as_uint(f);
    return (u & 0x80000000u) ? ~u : (u | 0x80000000u);
}
__device__ __forceinline__ float fdec(unsigned e) {
    unsigned u = (e & 0x80000000u) ? (e & 0x7FFFFFFFu) : ~e;
    return __uint_as_float(u);
}

// ---------------- CSR construction ----------------
__global__ void k_zero_csr() {
    int i = blockIdx.x * blockDim.x + threadIdx.x;
    if (i < ME) g_degE[i] = 0;
    if (i < NV) g_degV[i] = 0;
}

__global__ void k_count(const int* __restrict__ vi, const int* __restrict__ ei) {
    int i = blockIdx.x * blockDim.x + threadIdx.x;
    if (i < EI) {
        atomicAdd(&g_degV[vi[i]], 1);
        atomicAdd(&g_degE[ei[i]], 1);
    }
}

// single-block exclusive scan (n <= 20000, 1024 threads)
__global__ void k_scan(const int* __restrict__ cnt, int* __restrict__ off,
                       int* __restrict__ cur, int n) {
    __shared__ int part[1024];
    int T = blockDim.x, tid = threadIdx.x;
    int chunk = (n + T - 1) / T;
    int beg = tid * chunk;
    int end = min(beg + chunk, n);
    int s = 0;
    for (int i = beg; i < end; ++i) s += cnt[i];
    part[tid] = s;
    __syncthreads();
    if (tid == 0) {
        int run = 0;
        for (int t = 0; t < T; ++t) { int tmp = part[t]; part[t] = run; run += tmp; }
    }
    __syncthreads();
    int run = part[tid];
    for (int i = beg; i < end; ++i) { off[i] = run; cur[i] = run; run += cnt[i]; }
    if (end == n) off[n] = run;   // threads past the end write total (same value)
}

__global__ void k_fill(const int* __restrict__ vi, const int* __restrict__ ei) {
    int i = blockIdx.x * blockDim.x + threadIdx.x;
    if (i < EI) {
        int v = vi[i], e = ei[i];
        g_elist[atomicAdd(&g_ecur[e], 1)] = v;
        g_vlist[atomicAdd(&g_vcur[v], 1)] = e;
    }
}

// ---------------- SGEMM: C[M,N] = A[M,K] @ B[N,K]^T + bias ----------------
__global__ void __launch_bounds__(256)
k_sgemm_nt(const float* __restrict__ A, const float* __restrict__ B,
           const float* __restrict__ bias, float* __restrict__ C,
           int M, int N, int K) {
    const int BM = 128, BN = 128, BK = 8, TM = 8, TN = 8;
    __shared__ __align__(16) float As[BK][BM];
    __shared__ __align__(16) float Bs[BK][BN];
    int bm = blockIdx.y * BM, bn = blockIdx.x * BN;
    int tid = threadIdx.x;
    int tcol = (tid % 16) * TN;
    int trow = (tid / 16) * TM;
    float acc[TM][TN];
#pragma unroll
    for (int i = 0; i < TM; ++i)
#pragma unroll
        for (int j = 0; j < TN; ++j) acc[i][j] = 0.f;

    int lr = tid >> 1;
    int lc = (tid & 1) * 4;
    int arow = bm + lr;
    bool aval = arow < M;
    const float* Aptr = A + (size_t)(aval ? arow : 0) * K + lc;
    const float* Bptr = B + (size_t)(bn + lr) * K + lc;

    for (int k0 = 0; k0 < K; k0 += BK) {
        float4 av = aval ? *(const float4*)(Aptr + k0) : make_float4(0.f, 0.f, 0.f, 0.f);
        float4 bv = *(const float4*)(Bptr + k0);
        As[lc + 0][lr] = av.x; As[lc + 1][lr] = av.y;
        As[lc + 2][lr] = av.z; As[lc + 3][lr] = av.w;
        Bs[lc + 0][lr] = bv.x; Bs[lc + 1][lr] = bv.y;
        Bs[lc + 2][lr] = bv.z; Bs[lc + 3][lr] = bv.w;
        __syncthreads();
#pragma unroll
        for (int k = 0; k < BK; ++k) {
            float4 a0 = *(const float4*)&As[k][trow];
            float4 a1 = *(const float4*)&As[k][trow + 4];
            float4 b0 = *(const float4*)&Bs[k][tcol];
            float4 b1 = *(const float4*)&Bs[k][tcol + 4];
            float ar[8] = {a0.x, a0.y, a0.z, a0.w, a1.x, a1.y, a1.z, a1.w};
            float br[8] = {b0.x, b0.y, b0.z, b0.w, b1.x, b1.y, b1.z, b1.w};
#pragma unroll
            for (int i = 0; i < TM; ++i)
#pragma unroll
                for (int j = 0; j < TN; ++j) acc[i][j] += ar[i] * br[j];
        }
        __syncthreads();
    }
#pragma unroll
    for (int i = 0; i < TM; ++i) {
        int r = bm + trow + i;
        if (r >= M) continue;
#pragma unroll
        for (int j = 0; j < TN; ++j) {
            int c = bn + tcol + j;
            float v = acc[i][j];
            if (bias) v += bias[c];
            C[(size_t)r * N + c] = v;
        }
    }
}

// ---------------- v2e mean (+ optional edge attention logit) ----------------
template <int D>
__global__ void __launch_bounds__(256)
k_v2e(const float* __restrict__ Hp, const float* __restrict__ we,
      float* __restrict__ Y, float* __restrict__ alpha) {
    int e = blockIdx.x;
    int beg = g_eoff[e], end = g_eoff[e + 1];
    const int NCOL = D / 256;
    float acc[NCOL];
#pragma unroll
    for (int c = 0; c < NCOL; ++c) acc[c] = 0.f;
    for (int t = beg; t < end; ++t) {
        const float* row = Hp + (size_t)g_elist[t] * D;
#pragma unroll
        for (int c = 0; c < NCOL; ++c) acc[c] += row[threadIdx.x + c * 256];
    }
    float inv = 1.f / fmaxf((float)(end - beg), 1.f);
    float dot = 0.f;
#pragma unroll
    for (int c = 0; c < NCOL; ++c) {
        float yv = acc[c] * inv;
        Y[(size_t)e * D + threadIdx.x + c * 256] = yv;
        if (we) dot += yv * we[threadIdx.x + c * 256];
    }
    if (we) {
        __shared__ float red[256];
        red[threadIdx.x] = dot;
        __syncthreads();
        for (int s = 128; s > 0; s >>= 1) {
            if (threadIdx.x < s) red[threadIdx.x] += red[threadIdx.x + s];
            __syncthreads();
        }
        if (threadIdx.x == 0) alpha[e] = red[0];
    }
}

// ---------------- per-vertex softmax stats over incident edges ----------------
__global__ void k_vstats() {
    int v = blockIdx.x * blockDim.x + threadIdx.x;
    if (v >= NV) return;
    int beg = g_voff[v], end = g_voff[v + 1];
    float m = -INFINITY;
    for (int t = beg; t < end; ++t) {
        float a = g_alpha[g_vlist[t]];
        a = a > 0.f ? a : 0.2f * a;
        m = fmaxf(m, a);
    }
    float s = 0.f;
    for (int t = beg; t < end; ++t) {
        float a = g_alpha[g_vlist[t]];
        a = a > 0.f ? a : 0.2f * a;
        s += expf(a - m);
    }
    g_vm[v] = m;
    g_vwinv[v] = 1.f / (s + 1e-12f);
}

// ---------------- e2v: softmax-weighted sum of edge features ----------------
template <int D, bool ELU>
__global__ void __launch_bounds__(256)
k_e2v(const float* __restrict__ Y, float* __restrict__ Xo) {
    int v = blockIdx.x;
    int beg = g_voff[v], end = g_voff[v + 1];
    const int NCOL = D / 256;
    float acc[NCOL];
#pragma unroll
    for (int c = 0; c < NCOL; ++c) acc[c] = 0.f;
    float m = g_vm[v], winv = g_vwinv[v];
    for (int t = beg; t < end; ++t) {
        int e = g_vlist[t];
        float a = g_alpha[e];
        a = a > 0.f ? a : 0.2f * a;
        float w = expf(a - m) * winv;
        const float* yr = Y + (size_t)e * D;
#pragma unroll
        for (int c = 0; c < NCOL; ++c) acc[c] += w * yr[threadIdx.x + c * 256];
    }
#pragma unroll
    for (int c = 0; c < NCOL; ++c) {
        float x = acc[c];
        if (ELU) x = x > 0.f ? x : expm1f(x);
        Xo[(size_t)v * D + threadIdx.x + c * 256] = x;
    }
}

// ---------------- gated attention pieces ----------------
__global__ void __launch_bounds__(256)
k_logits(const float* __restrict__ AB, const float* __restrict__ ba,
         const float* __restrict__ bb, const float* __restrict__ Wc,
         const float* __restrict__ bc, float* __restrict__ logit) {
    int r = blockIdx.x, j = threadIdx.x;
    float av = tanhf(AB[(size_t)r * 512 + j] + ba[j]);
    float bv = AB[(size_t)r * 512 + 256 + j] + bb[j];
    float sg = 1.f / (1.f + expf(-bv));
    float v = av * sg * Wc[j];
    __shared__ float red[256];
    red[j] = v;
    __syncthreads();
    for (int s = 128; s > 0; s >>= 1) {
        if (j < s) red[j] += red[j + s];
        __syncthreads();
    }
    if (j == 0) logit[r] = red[0] + bc[0];
}

__global__ void k_attn_init() {
    int i = blockIdx.x * blockDim.x + threadIdx.x;
    if (i < CDIM) g_gvec[i] = 0.f;
    if (i == 0) { g_menc = 0u; g_S = 0.f; }
}

__global__ void __launch_bounds__(256)
k_maxred(const float* __restrict__ l, int n) {
    float m = -INFINITY;
    for (int i = blockIdx.x * blockDim.x + threadIdx.x; i < n; i += gridDim.x * blockDim.x)
        m = fmaxf(m, l[i]);
    __shared__ float red[256];
    red[threadIdx.x] = m;
    __syncthreads();
    for (int s = 128; s > 0; s >>= 1) {
        if (threadIdx.x < s) red[threadIdx.x] = fmaxf(red[threadIdx.x], red[threadIdx.x + s]);
        __syncthreads();
    }
    if (threadIdx.x == 0) atomicMax(&g_menc, fenc(red[0]));
}

__global__ void __launch_bounds__(256)
k_sumexp(const float* __restrict__ l, int n) {
    float m = fdec(g_menc);
    float s = 0.f;
    for (int i = blockIdx.x * blockDim.x + threadIdx.x; i < n; i += gridDim.x * blockDim.x)
        s += expf(l[i] - m);
    __shared__ float red[256];
    red[threadIdx.x] = s;
    __syncthreads();
    for (int st = 128; st > 0; st >>= 1) {
        if (threadIdx.x < st) red[threadIdx.x] += red[threadIdx.x + st];
        __syncthreads();
    }
    if (threadIdx.x == 0) atomicAdd(&g_S, red[0]);
}

__global__ void __launch_bounds__(256)
k_wsum(const float* __restrict__ x, const float* __restrict__ l, int n) {
    int c = blockIdx.x * 256 + threadIdx.x;       // gridDim.x = CDIM/256
    float m = fdec(g_menc);
    float invS = 1.f / g_S;
    float acc = 0.f;
    for (int r = blockIdx.y; r < n; r += gridDim.y)
        acc += expf(l[r] - m) * invS * x[(size_t)r * CDIM + c];
    atomicAdd(&g_gvec[c], acc);
}

__global__ void k_gemv(const float* __restrict__ v, const float* __restrict__ W,
                       const float* __restrict__ b, float* __restrict__ out,
                       int R, int K) {
    int row = blockIdx.x * (blockDim.x >> 5) + (threadIdx.x >> 5);
    if (row >= R) return;
    int lane = threadIdx.x & 31;
    const float* wr = W + (size_t)row * K;
    float s = 0.f;
    for (int k = lane; k < K; k += 32) s += v[k] * wr[k];
    for (int o = 16; o; o >>= 1) s += __shfl_down_sync(0xffffffffu, s, o);
    if (lane == 0) out[row] = s + b[row];
}

__global__ void __launch_bounds__(256)
k_ln(const float* __restrict__ x, const float* __restrict__ g,
     const float* __restrict__ b, float* __restrict__ out, int D) {
    __shared__ float red[256];
    __shared__ float mu_s, rstd_s;
    float s = 0.f;
    for (int i = threadIdx.x; i < D; i += 256) s += x[i];
    red[threadIdx.x] = s;
    __syncthreads();
    for (int st = 128; st > 0; st >>= 1) {
        if (threadIdx.x < st) red[threadIdx.x] += red[threadIdx.x + st];
        __syncthreads();
    }
    if (threadIdx.x == 0) mu_s = red[0] / (float)D;
    __syncthreads();
    float mu = mu_s;
    float vs = 0.f;
    for (int i = threadIdx.x; i < D; i += 256) {
        float d = x[i] - mu;
        vs += d * d;
    }
    red[threadIdx.x] = vs;
    __syncthreads();
    for (int st = 128; st > 0; st >>= 1) {
        if (threadIdx.x < st) red[threadIdx.x] += red[threadIdx.x + st];
        __syncthreads();
    }
    if (threadIdx.x == 0) rstd_s = rsqrtf(red[0] / (float)D + 1e-5f);
    __syncthreads();
    float rstd = rstd_s;
    for (int i = threadIdx.x; i < D; i += 256)
        out[i] = (x[i] - mu) * rstd * g[i] + b[i];
}

// ---------------- host orchestration ----------------
extern "C" void kernel_launch(void* const* d_in, const int* in_sizes, int n_in,
                              void* d_out, int out_size) {
    // resolve scratch addresses
    float *bufA, *bufB, *bufC, *bufD, *Y, *ybuf, *ABy, *alpha, *logits;
    float *Wab, *gvec, *gout, *gcat, *gcatn;
    int *degE, *degV, *eoff, *voff, *ecur, *vcur;
    cudaGetSymbolAddress((void**)&bufA, g_bufA);
    cudaGetSymbolAddress((void**)&bufB, g_bufB);
    cudaGetSymbolAddress((void**)&bufC, g_bufC);
    cudaGetSymbolAddress((void**)&bufD, g_bufD);
    cudaGetSymbolAddress((void**)&Y, g_Y);
    cudaGetSymbolAddress((void**)&ybuf, g_ybuf);
    cudaGetSymbolAddress((void**)&ABy, g_ABy);
    cudaGetSymbolAddress((void**)&alpha, g_alpha);
    cudaGetSymbolAddress((void**)&logits, g_logits);
    cudaGetSymbolAddress((void**)&Wab, g_Wab);
    cudaGetSymbolAddress((void**)&gvec, g_gvec);
    cudaGetSymbolAddress((void**)&gout, g_gout);
    cudaGetSymbolAddress((void**)&gcat, g_gcat);
    cudaGetSymbolAddress((void**)&gcatn, g_gcatn);
    cudaGetSymbolAddress((void**)&degE, g_degE);
    cudaGetSymbolAddress((void**)&degV, g_degV);
    cudaGetSymbolAddress((void**)&eoff, g_eoff);
    cudaGetSymbolAddress((void**)&voff, g_voff);
    cudaGetSymbolAddress((void**)&ecur, g_ecur);
    cudaGetSymbolAddress((void**)&vcur, g_vcur);

    // input index map: signature order (X0,X1,X2,v0,e0,v1,e1,v2,e2) vs
    // dict order (X0,v0,e0,X1,v1,e1,X2,v2,e2). Distinguish by in_sizes[1].
    int xi[3], vii[3], eii[3];
    if (in_sizes[1] == NV * CDIM) {
        for (int b = 0; b < 3; ++b) { xi[b] = b; vii[b] = 3 + 2 * b; eii[b] = 4 + 2 * b; }
    } else {
        for (int b = 0; b < 3; ++b) { xi[b] = 3 * b; vii[b] = 3 * b + 1; eii[b] = 3 * b + 2; }
    }
    const float* Wt0  = (const float*)d_in[9];
    const float* bt0  = (const float*)d_in[10];
    const float* we0  = (const float*)d_in[11];
    const float* Wt1  = (const float*)d_in[12];
    const float* bt1  = (const float*)d_in[13];
    const float* we1  = (const float*)d_in[14];
    const float* Wa   = (const float*)d_in[15];
    const float* ba   = (const float*)d_in[16];
    const float* Wb   = (const float*)d_in[17];
    const float* bb   = (const float*)d_in[18];
    const float* Wc   = (const float*)d_in[19];
    const float* bc   = (const float*)d_in[20];
    const float* Wout = (const float*)d_in[21];
    const float* bout = (const float*)d_in[22];
    const float* gbn  = (const float*)d_in[23];
    const float* bbn  = (const float*)d_in[24];
    const float* gbn2 = (const float*)d_in[25];
    const float* bbn2 = (const float*)d_in[26];
    const float* Wf   = (const float*)d_in[27];
    const float* bf   = (const float*)d_in[28];

    // build [Wa;Wb] once
    cudaMemcpyAsync(Wab, Wa, (size_t)256 * 1024 * sizeof(float),
                    cudaMemcpyDeviceToDevice, 0);
    cudaMemcpyAsync(Wab + 256 * 1024, Wb, (size_t)256 * 1024 * sizeof(float),
                    cudaMemcpyDeviceToDevice, 0);

    const int EB = (EI + 255) / 256;

    for (int b = 0; b < 3; ++b) {
        const float* X = (const float*)d_in[xi[b]];
        const int* vi = (const int*)d_in[vii[b]];
        const int* ei = (const int*)d_in[eii[b]];

        // ----- CSR -----
        k_zero_csr<<<(NV + 255) / 256, 256>>>();
        k_count<<<EB, 256>>>(vi, ei);
        k_scan<<<1, 1024>>>(degE, eoff, ecur, ME);
        k_scan<<<1, 1024>>>(degV, voff, vcur, NV);
        k_fill<<<EB, 256>>>(vi, ei);

        // ----- layer 1 (C -> HID, elu) -----
        {
            dim3 g(HIDD / 128, (NV + 127) / 128);
            k_sgemm_nt<<<g, 256>>>(X, Wt0, bt0, bufA, NV, HIDD, CDIM);
        }
        k_v2e<HIDD><<<ME, 256>>>(bufA, we0, Y, alpha);
        k_vstats<<<(NV + 255) / 256, 256>>>();
        k_e2v<HIDD, true><<<NV, 256>>>(Y, bufB);

        // ----- layer 2 (HID -> C, no elu) -----
        {
            dim3 g(CDIM / 128, (NV + 127) / 128);
            k_sgemm_nt<<<g, 256>>>(bufB, Wt1, bt1, bufC, NV, CDIM, HIDD);
        }
        k_v2e<CDIM><<<ME, 256>>>(bufC, we1, Y, alpha);
        k_vstats<<<(NV + 255) / 256, 256>>>();
        k_e2v<CDIM, false><<<NV, 256>>>(Y, bufD);

        // ----- y = v2e_mean(h) -----
        k_v2e<CDIM><<<ME, 256>>>(bufD, (const float*)nullptr, ybuf, alpha);

        // ----- gated attention on h (20000 rows) -----
        {
            dim3 g(512 / 128, (NV + 127) / 128);
            k_sgemm_nt<<<g, 256>>>(bufD, Wab, (const float*)nullptr, bufA, NV, 512, CDIM);
        }
        k_logits<<<NV, 256>>>(bufA, ba, bb, Wc, bc, logits);
        k_attn_init<<<4, 256>>>();
        k_maxred<<<40, 256>>>(logits, NV);
        k_sumexp<<<40, 256>>>(logits, NV);
        {
            dim3 g(CDIM / 256, 125);
            k_wsum<<<g, 256>>>(bufD, logits, NV);
        }
        k_gemv<<<128, 256>>>(gvec, Wout, bout, gout, CDIM, CDIM);
        k_ln<<<1, 256>>>(gout, gbn, bbn, gcat + (size_t)b * CDIM, CDIM);

        // ----- gated attention on y (5000 rows) -----
        {
            dim3 g(512 / 128, (ME + 127) / 128);
            k_sgemm_nt<<<g, 256>>>(ybuf, Wab, (const float*)nullptr, ABy, ME, 512, CDIM);
        }
        k_logits<<<ME, 256>>>(ABy, ba, bb, Wc, bc, logits);
        k_attn_init<<<4, 256>>>();
        k_maxred<<<20, 256>>>(logits, ME);
        k_sumexp<<<20, 256>>>(logits, ME);
        {
            dim3 g(CDIM / 256, 125);
            k_wsum<<<g, 256>>>(ybuf, logits, ME);
        }
        k_gemv<<<128, 256>>>(gvec, Wout, bout, gout, CDIM, CDIM);
        k_ln<<<1, 256>>>(gout, gbn, bbn, gcat + (size_t)(3 + b) * CDIM, CDIM);
    }

    // ----- final: LN(concat) @ Wf^T + bf -----
    k_ln<<<1, 256>>>(gcat, gbn2, bbn2, gcatn, 6 * CDIM);
    k_gemv<<<2, 256>>>(gcatn, Wf, bf, (float*)d_out, 10, 6 * CDIM);
}

// round 3
// speedup vs baseline: 2.0611x; 2.0611x over previous
#include <cuda_runtime.h>
#include <cuda_bf16.h>
#include <math.h>
#include <stdint.h>

// Problem constants
#define NV   20000
#define ME   5000
#define EI   160000
#define CDIM 1024
#define HIDD 512

// ---------------- device scratch (static, no allocation) ----------------
__device__ __align__(16) float g_bufA[(size_t)NV * HIDD];
__device__ __align__(16) float g_bufB[(size_t)NV * HIDD];
__device__ __align__(16) float g_bufC[(size_t)NV * CDIM];
__device__ __align__(16) float g_bufD[(size_t)NV * CDIM];
__device__ __align__(16) float g_Y[(size_t)ME * CDIM];
__device__ __align__(16) float g_ybuf[(size_t)ME * CDIM];
__device__ __align__(16) float g_ABy[(size_t)ME * HIDD];
__device__ float g_alpha[ME];
__device__ float g_vm[NV];
__device__ float g_vwinv[NV];
__device__ float g_logits[NV];

__device__ int g_degE[ME], g_eoff[ME + 1], g_ecur[ME];
__device__ int g_degV[NV], g_voff[NV + 1], g_vcur[NV];
__device__ int g_elist[EI];
__device__ int g_vlist[EI];

__device__ __align__(16) float g_Wab[512 * 1024];
__device__ float g_gvec[CDIM];
__device__ float g_gout[CDIM];
__device__ float g_gcat[6 * CDIM];
__device__ float g_gcatn[6 * CDIM];
__device__ unsigned g_menc;
__device__ float g_S;

// bf16 split buffers (16B-aligned for cp.async)
__device__ __align__(16) __nv_bfloat16 g_Acthi[(size_t)NV * CDIM];
__device__ __align__(16) __nv_bfloat16 g_Actlo[(size_t)NV * CDIM];
__device__ __align__(16) __nv_bfloat16 g_Wt0hi[512 * 1024], g_Wt0lo[512 * 1024];
__device__ __align__(16) __nv_bfloat16 g_Wt1hi[1024 * 512], g_Wt1lo[1024 * 512];
__device__ __align__(16) __nv_bfloat16 g_Wabhi[512 * 1024], g_Wablo[512 * 1024];

// ---------------- helpers ----------------
__device__ __forceinline__ uint32_t smem_u32(const void* p) {
    uint32_t a;
    asm("{ .reg .u64 t; cvta.to.shared.u64 t, %1; cvt.u32.u64 %0, t; }"
        : "=r"(a) : "l"(p));
    return a;
}

__device__ __forceinline__ void cp_cg(uint32_t s, const void* g, int bytes) {
    asm volatile("cp.async.cg.shared.global [%0], [%1], 16, %2;"
                 :: "r"(s), "l"(g), "r"(bytes) : "memory");
}

__device__ __forceinline__ void ldsm4(uint32_t* r, uint32_t addr) {
    asm volatile("ldmatrix.sync.aligned.m8n8.x4.shared.b16 {%0,%1,%2,%3}, [%4];"
                 : "=r"(r[0]), "=r"(r[1]), "=r"(r[2]), "=r"(r[3]) : "r"(addr));
}

__device__ __forceinline__ void mma16816(float* d, const uint32_t* a, const uint32_t* b) {
    asm volatile(
        "mma.sync.aligned.m16n8k16.row.col.f32.bf16.bf16.f32 "
        "{%0,%1,%2,%3}, {%4,%5,%6,%7}, {%8,%9}, {%0,%1,%2,%3};"
        : "+f"(d[0]), "+f"(d[1]), "+f"(d[2]), "+f"(d[3])
        : "r"(a[0]), "r"(a[1]), "r"(a[2]), "r"(a[3]), "r"(b[0]), "r"(b[1]));
}

__device__ __forceinline__ unsigned fenc(float f) {
    unsigned u = __float_as_uint(f);
    return (u & 0x80000000u) ? ~u : (u | 0x80000000u);
}
__device__ __forceinline__ float fdec(unsigned e) {
    unsigned u = (e & 0x80000000u) ? (e & 0x7FFFFFFFu) : ~e;
    return __uint_as_float(u);
}

// ---------------- fp32 -> bf16 hi/lo split ----------------
__global__ void __launch_bounds__(256)
k_split(const float* __restrict__ src, __nv_bfloat16* __restrict__ hi,
        __nv_bfloat16* __restrict__ lo, int n4) {
    int i = blockIdx.x * blockDim.x + threadIdx.x;
    if (i >= n4) return;
    float4 v = ((const float4*)src)[i];
    __nv_bfloat16 h[4], l[4];
    float x[4] = {v.x, v.y, v.z, v.w};
#pragma unroll
    for (int j = 0; j < 4; ++j) {
        h[j] = __float2bfloat16(x[j]);
        l[j] = __float2bfloat16(x[j] - __bfloat162float(h[j]));
    }
    ((__nv_bfloat162*)hi)[2 * i]     = __nv_bfloat162(h[0], h[1]);
    ((__nv_bfloat162*)hi)[2 * i + 1] = __nv_bfloat162(h[2], h[3]);
    ((__nv_bfloat162*)lo)[2 * i]     = __nv_bfloat162(l[0], l[1]);
    ((__nv_bfloat162*)lo)[2 * i + 1] = __nv_bfloat162(l[2], l[3]);
}

// ---------------- split-bf16 tensor-core GEMM: C = A @ B^T + bias ----------
// A: [M,K] hi/lo bf16 row-major; B: [N,K] hi/lo bf16 row-major.
// Tile 128x128x32, 256 threads, 8 warps (4 along M x 2 along N), warp 32x64.
// Smem stage: Ahi@0, Alo@10240, Bhi@20480, Blo@30720 (row stride 80B), 40960/stage.
__global__ void __launch_bounds__(256, 1)
k_mma_gemm(const __nv_bfloat16* __restrict__ Ahi, const __nv_bfloat16* __restrict__ Alo,
           const __nv_bfloat16* __restrict__ Bhi, const __nv_bfloat16* __restrict__ Blo,
           const float* __restrict__ bias, float* __restrict__ C,
           int M, int N, int K) {
    extern __shared__ char smraw[];
    uint32_t sb = smem_u32(smraw);
    const int STG = 40960;
    int tid = threadIdx.x, lane = tid & 31, warp = tid >> 5;
    int wm = (warp & 3) * 32;
    int wn = (warp >> 2) * 64;
    int bm = blockIdx.y * 128, bn = blockIdx.x * 128;

    float acc[2][8][4];
#pragma unroll
    for (int a = 0; a < 2; ++a)
#pragma unroll
        for (int b = 0; b < 8; ++b)
#pragma unroll
            for (int c = 0; c < 4; ++c) acc[a][b][c] = 0.f;

    auto issue = [&](int kt, int s) {
        int k0 = kt * 32;
        uint32_t sbase = sb + s * STG;
#pragma unroll
        for (int i = 0; i < 2; ++i) {
            int idx = i * 256 + tid;
            int row = idx >> 2, c = idx & 3;
            uint32_t soff = sbase + row * 80 + c * 16;
            int ar = bm + row;
            int pa = (ar < M) ? 16 : 0;
            int arc = (ar < M) ? ar : 0;
            cp_cg(soff,          Ahi + (size_t)arc * K + k0 + c * 8, pa);
            cp_cg(soff + 10240,  Alo + (size_t)arc * K + k0 + c * 8, pa);
            cp_cg(soff + 20480,  Bhi + (size_t)(bn + row) * K + k0 + c * 8, 16);
            cp_cg(soff + 30720,  Blo + (size_t)(bn + row) * K + k0 + c * 8, 16);
        }
        asm volatile("cp.async.commit_group;" ::: "memory");
    };

    int KT = K / 32;
    issue(0, 0);
    for (int kt = 0; kt < KT; ++kt) {
        int s = kt & 1;
        if (kt + 1 < KT) {
            issue(kt + 1, s ^ 1);
            asm volatile("cp.async.wait_group 1;" ::: "memory");
        } else {
            asm volatile("cp.async.wait_group 0;" ::: "memory");
        }
        __syncthreads();
        uint32_t sbase = sb + s * STG;
#pragma unroll
        for (int kk = 0; kk < 2; ++kk) {
            uint32_t ah[2][4], al[2][4];
#pragma unroll
            for (int mt = 0; mt < 2; ++mt) {
                uint32_t addr = sbase + (uint32_t)(wm + mt * 16 + (lane & 15)) * 80
                              + kk * 32 + (lane >> 4) * 16;
                ldsm4(ah[mt], addr);
                ldsm4(al[mt], addr + 10240);
            }
            uint32_t bh[8][2], bl[8][2];
#pragma unroll
            for (int np = 0; np < 4; ++np) {
                int row = wn + np * 16 + (lane & 7) + ((lane >> 4) << 3);
                uint32_t addr = sbase + 20480 + (uint32_t)row * 80
                              + kk * 32 + ((lane >> 3) & 1) * 16;
                uint32_t t[4];
                ldsm4(t, addr);
                bh[np * 2][0] = t[0]; bh[np * 2][1] = t[1];
                bh[np * 2 + 1][0] = t[2]; bh[np * 2 + 1][1] = t[3];
                ldsm4(t, addr + 10240);
                bl[np * 2][0] = t[0]; bl[np * 2][1] = t[1];
                bl[np * 2 + 1][0] = t[2]; bl[np * 2 + 1][1] = t[3];
            }
#pragma unroll
            for (int mt = 0; mt < 2; ++mt)
#pragma unroll
                for (int nt = 0; nt < 8; ++nt) {
                    mma16816(acc[mt][nt], ah[mt], bh[nt]);
                    mma16816(acc[mt][nt], ah[mt], bl[nt]);
                    mma16816(acc[mt][nt], al[mt], bh[nt]);
                }
        }
        __syncthreads();
    }

    // epilogue: direct register -> GMEM (8B per thread-quad write)
#pragma unroll
    for (int mt = 0; mt < 2; ++mt) {
        int r0 = bm + wm + mt * 16 + (lane >> 2);
#pragma unroll
        for (int nt = 0; nt < 8; ++nt) {
            int c0 = bn + wn + nt * 8 + (lane & 3) * 2;
            float bx = bias ? __ldg(bias + c0) : 0.f;
            float by = bias ? __ldg(bias + c0 + 1) : 0.f;
            if (r0 < M) {
                float2 v = make_float2(acc[mt][nt][0] + bx, acc[mt][nt][1] + by);
                *(float2*)(C + (size_t)r0 * N + c0) = v;
            }
            if (r0 + 8 < M) {
                float2 v = make_float2(acc[mt][nt][2] + bx, acc[mt][nt][3] + by);
                *(float2*)(C + (size_t)(r0 + 8) * N + c0) = v;
            }
        }
    }
}

// ---------------- CSR construction ----------------
__global__ void k_zero_csr() {
    int i = blockIdx.x * blockDim.x + threadIdx.x;
    if (i < ME) g_degE[i] = 0;
    if (i < NV) g_degV[i] = 0;
}

__global__ void k_count(const int* __restrict__ vi, const int* __restrict__ ei) {
    int i = blockIdx.x * blockDim.x + threadIdx.x;
    if (i < EI) {
        atomicAdd(&g_degV[vi[i]], 1);
        atomicAdd(&g_degE[ei[i]], 1);
    }
}

__global__ void __launch_bounds__(1024)
k_scan(const int* __restrict__ cnt, int* __restrict__ off,
       int* __restrict__ cur, int n) {
    __shared__ int wsum[32];
    int tid = threadIdx.x, lane = tid & 31, w = tid >> 5;
    int chunk = (n + 1023) / 1024;
    int beg = min(tid * chunk, n);
    int end = min(beg + chunk, n);
    int s = 0;
    for (int i = beg; i < end; ++i) s += cnt[i];
    int v = s;
#pragma unroll
    for (int o = 1; o < 32; o <<= 1) {
        int u = __shfl_up_sync(0xffffffffu, v, o);
        if (lane >= o) v += u;
    }
    if (lane == 31) wsum[w] = v;
    __syncthreads();
    if (w == 0) {
        int ws = wsum[lane];
#pragma unroll
        for (int o = 1; o < 32; o <<= 1) {
            int u = __shfl_up_sync(0xffffffffu, ws, o);
            if (lane >= o) ws += u;
        }
        wsum[lane] = ws;
    }
    __syncthreads();
    int excl = v - s + (w > 0 ? wsum[w - 1] : 0);
    int run = excl;
    for (int i = beg; i < end; ++i) { off[i] = run; cur[i] = run; run += cnt[i]; }
    if (tid == 1023) off[n] = wsum[31];
}

__global__ void k_fill(const int* __restrict__ vi, const int* __restrict__ ei) {
    int i = blockIdx.x * blockDim.x + threadIdx.x;
    if (i < EI) {
        int v = vi[i], e = ei[i];
        g_elist[atomicAdd(&g_ecur[e], 1)] = v;
        g_vlist[atomicAdd(&g_vcur[v], 1)] = e;
    }
}

// ---------------- v2e mean (+ optional edge attention logit) ----------------
template <int D, bool WE>
__global__ void __launch_bounds__(D / 4)
k_v2e(const float* __restrict__ Hp, const float* __restrict__ we,
      float* __restrict__ Y, float* __restrict__ alpha) {
    constexpr int T = D / 4;
    int e = blockIdx.x;
    int beg = g_eoff[e], end = g_eoff[e + 1];
    int t = threadIdx.x;
    float4 acc = make_float4(0.f, 0.f, 0.f, 0.f);
    for (int i = beg; i < end; ++i) {
        const float4* row = (const float4*)(Hp + (size_t)g_elist[i] * D);
        float4 v = row[t];
        acc.x += v.x; acc.y += v.y; acc.z += v.z; acc.w += v.w;
    }
    float inv = 1.f / fmaxf((float)(end - beg), 1.f);
    float4 y = make_float4(acc.x * inv, acc.y * inv, acc.z * inv, acc.w * inv);
    ((float4*)(Y + (size_t)e * D))[t] = y;
    if (WE) {
        float4 w4 = ((const float4*)we)[t];
        float dot = y.x * w4.x + y.y * w4.y + y.z * w4.z + y.w * w4.w;
        __shared__ float red[T];
        red[t] = dot;
        __syncthreads();
        for (int s = T / 2; s > 0; s >>= 1) {
            if (t < s) red[t] += red[t + s];
            __syncthreads();
        }
        if (t == 0) alpha[e] = red[0];
    }
}

// ---------------- per-vertex softmax stats over incident edges ----------------
__global__ void k_vstats() {
    int v = blockIdx.x * blockDim.x + threadIdx.x;
    if (v >= NV) return;
    int beg = g_voff[v], end = g_voff[v + 1];
    float m = -INFINITY;
    for (int t = beg; t < end; ++t) {
        float a = g_alpha[g_vlist[t]];
        a = a > 0.f ? a : 0.2f * a;
        m = fmaxf(m, a);
    }
    float s = 0.f;
    for (int t = beg; t < end; ++t) {
        float a = g_alpha[g_vlist[t]];
        a = a > 0.f ? a : 0.2f * a;
        s += expf(a - m);
    }
    g_vm[v] = m;
    g_vwinv[v] = 1.f / (s + 1e-12f);
}

// ---------------- e2v: softmax-weighted sum of edge features ----------------
template <int D, bool ELU>
__global__ void __launch_bounds__(D / 4)
k_e2v(const float* __restrict__ Y, float* __restrict__ Xo) {
    int v = blockIdx.x;
    int beg = g_voff[v], end = g_voff[v + 1];
    int t = threadIdx.x;
    float4 acc = make_float4(0.f, 0.f, 0.f, 0.f);
    float m = g_vm[v], winv = g_vwinv[v];
    for (int i = beg; i < end; ++i) {
        int e = g_vlist[i];
        float a = g_alpha[e];
        a = a > 0.f ? a : 0.2f * a;
        float w = expf(a - m) * winv;
        float4 yv = ((const float4*)(Y + (size_t)e * D))[t];
        acc.x += w * yv.x; acc.y += w * yv.y; acc.z += w * yv.z; acc.w += w * yv.w;
    }
    if (ELU) {
        acc.x = acc.x > 0.f ? acc.x : expm1f(acc.x);
        acc.y = acc.y > 0.f ? acc.y : expm1f(acc.y);
        acc.z = acc.z > 0.f ? acc.z : expm1f(acc.z);
        acc.w = acc.w > 0.f ? acc.w : expm1f(acc.w);
    }
    ((float4*)(Xo + (size_t)v * D))[t] = acc;
}

// ---------------- gated attention pieces ----------------
__global__ void __launch_bounds__(256)
k_logits(const float* __restrict__ AB, const float* __restrict__ ba,
         const float* __restrict__ bb, const float* __restrict__ Wc,
         const float* __restrict__ bc, float* __restrict__ logit) {
    int r = blockIdx.x, j = threadIdx.x;
    float av = tanhf(AB[(size_t)r * 512 + j] + ba[j]);
    float bv = AB[(size_t)r * 512 + 256 + j] + bb[j];
    float sg = 1.f / (1.f + expf(-bv));
    float v = av * sg * Wc[j];
    __shared__ float red[256];
    red[j] = v;
    __syncthreads();
    for (int s = 128; s > 0; s >>= 1) {
        if (j < s) red[j] += red[j + s];
        __syncthreads();
    }
    if (j == 0) logit[r] = red[0] + bc[0];
}

__global__ void k_attn_init() {
    int i = blockIdx.x * blockDim.x + threadIdx.x;
    if (i < CDIM) g_gvec[i] = 0.f;
    if (i == 0) { g_menc = 0u; g_S = 0.f; }
}

__global__ void __launch_bounds__(256)
k_maxred(const float* __restrict__ l, int n) {
    float m = -INFINITY;
    for (int i = blockIdx.x * blockDim.x + threadIdx.x; i < n; i += gridDim.x * blockDim.x)
        m = fmaxf(m, l[i]);
    __shared__ float red[256];
    red[threadIdx.x] = m;
    __syncthreads();
    for (int s = 128; s > 0; s >>= 1) {
        if (threadIdx.x < s) red[threadIdx.x] = fmaxf(red[threadIdx.x], red[threadIdx.x + s]);
        __syncthreads();
    }
    if (threadIdx.x == 0) atomicMax(&g_menc, fenc(red[0]));
}

__global__ void __launch_bounds__(256)
k_sumexp(const float* __restrict__ l, int n) {
    float m = fdec(g_menc);
    float s = 0.f;
    for (int i = blockIdx.x * blockDim.x + threadIdx.x; i < n; i += gridDim.x * blockDim.x)
        s += expf(l[i] - m);
    __shared__ float red[256];
    red[threadIdx.x] = s;
    __syncthreads();
    for (int st = 128; st > 0; st >>= 1) {
        if (threadIdx.x < st) red[threadIdx.x] += red[threadIdx.x + st];
        __syncthreads();
    }
    if (threadIdx.x == 0) atomicAdd(&g_S, red[0]);
}

__global__ void __launch_bounds__(256)
k_wsum(const float* __restrict__ x, const float* __restrict__ l, int n) {
    int c = blockIdx.x * 256 + threadIdx.x;
    float m = fdec(g_menc);
    float invS = 1.f / g_S;
    float acc = 0.f;
    for (int r = blockIdx.y; r < n; r += gridDim.y)
        acc += expf(l[r] - m) * invS * x[(size_t)r * CDIM + c];
    atomicAdd(&g_gvec[c], acc);
}

__global__ void k_gemv(const float* __restrict__ v, const float* __restrict__ W,
                       const float* __restrict__ b, float* __restrict__ out,
                       int R, int K) {
    int row = blockIdx.x * (blockDim.x >> 5) + (threadIdx.x >> 5);
    if (row >= R) return;
    int lane = threadIdx.x & 31;
    const float* wr = W + (size_t)row * K;
    float s = 0.f;
    for (int k = lane; k < K; k += 32) s += v[k] * wr[k];
    for (int o = 16; o; o >>= 1) s += __shfl_down_sync(0xffffffffu, s, o);
    if (lane == 0) out[row] = s + b[row];
}

__global__ void __launch_bounds__(256)
k_ln(const float* __restrict__ x, const float* __restrict__ g,
     const float* __restrict__ b, float* __restrict__ out, int D) {
    __shared__ float red[256];
    __shared__ float mu_s, rstd_s;
    float s = 0.f;
    for (int i = threadIdx.x; i < D; i += 256) s += x[i];
    red[threadIdx.x] = s;
    __syncthreads();
    for (int st = 128; st > 0; st >>= 1) {
        if (threadIdx.x < st) red[threadIdx.x] += red[threadIdx.x + st];
        __syncthreads();
    }
    if (threadIdx.x == 0) mu_s = red[0] / (float)D;
    __syncthreads();
    float mu = mu_s;
    float vs = 0.f;
    for (int i = threadIdx.x; i < D; i += 256) {
        float d = x[i] - mu;
        vs += d * d;
    }
    red[threadIdx.x] = vs;
    __syncthreads();
    for (int st = 128; st > 0; st >>= 1) {
        if (threadIdx.x < st) red[threadIdx.x] += red[threadIdx.x + st];
        __syncthreads();
    }
    if (threadIdx.x == 0) rstd_s = rsqrtf(red[0] / (float)D + 1e-5f);
    __syncthreads();
    float rstd = rstd_s;
    for (int i = threadIdx.x; i < D; i += 256)
        out[i] = (x[i] - mu) * rstd * g[i] + b[i];
}

// ---------------- host orchestration ----------------
extern "C" void kernel_launch(void* const* d_in, const int* in_sizes, int n_in,
                              void* d_out, int out_size) {
    float *bufA, *bufB, *bufC, *bufD, *Y, *ybuf, *ABy, *alpha, *logits;
    float *Wab, *gvec, *gout, *gcat, *gcatn;
    int *degE, *degV, *eoff, *voff, *ecur, *vcur;
    __nv_bfloat16 *Acthi, *Actlo, *Wt0hi, *Wt0lo, *Wt1hi, *Wt1lo, *Wabhi, *Wablo;
    cudaGetSymbolAddress((void**)&bufA, g_bufA);
    cudaGetSymbolAddress((void**)&bufB, g_bufB);
    cudaGetSymbolAddress((void**)&bufC, g_bufC);
    cudaGetSymbolAddress((void**)&bufD, g_bufD);
    cudaGetSymbolAddress((void**)&Y, g_Y);
    cudaGetSymbolAddress((void**)&ybuf, g_ybuf);
    cudaGetSymbolAddress((void**)&ABy, g_ABy);
    cudaGetSymbolAddress((void**)&alpha, g_alpha);
    cudaGetSymbolAddress((void**)&logits, g_logits);
    cudaGetSymbolAddress((void**)&Wab, g_Wab);
    cudaGetSymbolAddress((void**)&gvec, g_gvec);
    cudaGetSymbolAddress((void**)&gout, g_gout);
    cudaGetSymbolAddress((void**)&gcat, g_gcat);
    cudaGetSymbolAddress((void**)&gcatn, g_gcatn);
    cudaGetSymbolAddress((void**)&degE, g_degE);
    cudaGetSymbolAddress((void**)&degV, g_degV);
    cudaGetSymbolAddress((void**)&eoff, g_eoff);
    cudaGetSymbolAddress((void**)&voff, g_voff);
    cudaGetSymbolAddress((void**)&ecur, g_ecur);
    cudaGetSymbolAddress((void**)&vcur, g_vcur);
    cudaGetSymbolAddress((void**)&Acthi, g_Acthi);
    cudaGetSymbolAddress((void**)&Actlo, g_Actlo);
    cudaGetSymbolAddress((void**)&Wt0hi, g_Wt0hi);
    cudaGetSymbolAddress((void**)&Wt0lo, g_Wt0lo);
    cudaGetSymbolAddress((void**)&Wt1hi, g_Wt1hi);
    cudaGetSymbolAddress((void**)&Wt1lo, g_Wt1lo);
    cudaGetSymbolAddress((void**)&Wabhi, g_Wabhi);
    cudaGetSymbolAddress((void**)&Wablo, g_Wablo);

    const int GSMEM = 81920;
    cudaFuncSetAttribute(k_mma_gemm, cudaFuncAttributeMaxDynamicSharedMemorySize, GSMEM);

    // input index map (signature vs dict order)
    int xi[3], vii[3], eii[3];
    if (in_sizes[1] == NV * CDIM) {
        for (int b = 0; b < 3; ++b) { xi[b] = b; vii[b] = 3 + 2 * b; eii[b] = 4 + 2 * b; }
    } else {
        for (int b = 0; b < 3; ++b) { xi[b] = 3 * b; vii[b] = 3 * b + 1; eii[b] = 3 * b + 2; }
    }
    const float* Wt0  = (const float*)d_in[9];
    const float* bt0  = (const float*)d_in[10];
    const float* we0  = (const float*)d_in[11];
    const float* Wt1  = (const float*)d_in[12];
    const float* bt1  = (const float*)d_in[13];
    const float* we1  = (const float*)d_in[14];
    const float* Wa   = (const float*)d_in[15];
    const float* ba   = (const float*)d_in[16];
    const float* Wb   = (const float*)d_in[17];
    const float* bb   = (const float*)d_in[18];
    const float* Wc   = (const float*)d_in[19];
    const float* bc   = (const float*)d_in[20];
    const float* Wout = (const float*)d_in[21];
    const float* bout = (const float*)d_in[22];
    const float* gbn  = (const float*)d_in[23];
    const float* bbn  = (const float*)d_in[24];
    const float* gbn2 = (const float*)d_in[25];
    const float* bbn2 = (const float*)d_in[26];
    const float* Wf   = (const float*)d_in[27];
    const float* bf   = (const float*)d_in[28];

    // assemble [Wa;Wb] and split all weights once
    cudaMemcpyAsync(Wab, Wa, (size_t)256 * 1024 * sizeof(float), cudaMemcpyDeviceToDevice, 0);
    cudaMemcpyAsync(Wab + 256 * 1024, Wb, (size_t)256 * 1024 * sizeof(float), cudaMemcpyDeviceToDevice, 0);
    k_split<<<512, 256>>>(Wt0, Wt0hi, Wt0lo, 512 * 1024 / 4);
    k_split<<<512, 256>>>(Wt1, Wt1hi, Wt1lo, 1024 * 512 / 4);
    k_split<<<512, 256>>>(Wab, Wabhi, Wablo, 512 * 1024 / 4);

    const int EB = (EI + 255) / 256;

    for (int b = 0; b < 3; ++b) {
        const float* X = (const float*)d_in[xi[b]];
        const int* vi = (const int*)d_in[vii[b]];
        const int* ei = (const int*)d_in[eii[b]];

        // ----- CSR -----
        k_zero_csr<<<(NV + 255) / 256, 256>>>();
        k_count<<<EB, 256>>>(vi, ei);
        k_scan<<<1, 1024>>>(degE, eoff, ecur, ME);
        k_scan<<<1, 1024>>>(degV, voff, vcur, NV);
        k_fill<<<EB, 256>>>(vi, ei);

        // ----- layer 1 (C -> HID, elu) -----
        k_split<<<(NV * CDIM / 4 + 255) / 256, 256>>>(X, Acthi, Actlo, NV * CDIM / 4);
        {
            dim3 g(HIDD / 128, (NV + 127) / 128);
            k_mma_gemm<<<g, 256, GSMEM>>>(Acthi, Actlo, Wt0hi, Wt0lo, bt0, bufA, NV, HIDD, CDIM);
        }
        k_v2e<HIDD, true><<<ME, HIDD / 4>>>(bufA, we0, Y, alpha);
        k_vstats<<<(NV + 255) / 256, 256>>>();
        k_e2v<HIDD, true><<<NV, HIDD / 4>>>(Y, bufB);

        // ----- layer 2 (HID -> C, no elu) -----
        k_split<<<(NV * HIDD / 4 + 255) / 256, 256>>>(bufB, Acthi, Actlo, NV * HIDD / 4);
        {
            dim3 g(CDIM / 128, (NV + 127) / 128);
            k_mma_gemm<<<g, 256, GSMEM>>>(Acthi, Actlo, Wt1hi, Wt1lo, bt1, bufC, NV, CDIM, HIDD);
        }
        k_v2e<CDIM, true><<<ME, CDIM / 4>>>(bufC, we1, Y, alpha);
        k_vstats<<<(NV + 255) / 256, 256>>>();
        k_e2v<CDIM, false><<<NV, CDIM / 4>>>(Y, bufD);

        // ----- y = v2e_mean(h) -----
        k_v2e<CDIM, false><<<ME, CDIM / 4>>>(bufD, (const float*)nullptr, ybuf, alpha);

        // ----- gated attention on h (20000 rows) -----
        k_split<<<(NV * CDIM / 4 + 255) / 256, 256>>>(bufD, Acthi, Actlo, NV * CDIM / 4);
        {
            dim3 g(512 / 128, (NV + 127) / 128);
            k_mma_gemm<<<g, 256, GSMEM>>>(Acthi, Actlo, Wabhi, Wablo,
                                          (const float*)nullptr, bufA, NV, 512, CDIM);
        }
        k_logits<<<NV, 256>>>(bufA, ba, bb, Wc, bc, logits);
        k_attn_init<<<4, 256>>>();
        k_maxred<<<40, 256>>>(logits, NV);
        k_sumexp<<<40, 256>>>(logits, NV);
        {
            dim3 g(CDIM / 256, 125);
            k_wsum<<<g, 256>>>(bufD, logits, NV);
        }
        k_gemv<<<128, 256>>>(gvec, Wout, bout, gout, CDIM, CDIM);
        k_ln<<<1, 256>>>(gout, gbn, bbn, gcat + (size_t)b * CDIM, CDIM);

        // ----- gated attention on y (5000 rows) -----
        k_split<<<(ME * CDIM / 4 + 255) / 256, 256>>>(ybuf, Acthi, Actlo, ME * CDIM / 4);
        {
            dim3 g(512 / 128, (ME + 127) / 128);
            k_mma_gemm<<<g, 256, GSMEM>>>(Acthi, Actlo, Wabhi, Wablo,
                                          (const float*)nullptr, ABy, ME, 512, CDIM);
        }
        k_logits<<<ME, 256>>>(ABy, ba, bb, Wc, bc, logits);
        k_attn_init<<<4, 256>>>();
        k_maxred<<<20, 256>>>(logits, ME);
        k_sumexp<<<20, 256>>>(logits, ME);
        {
            dim3 g(CDIM / 256, 125);
            k_wsum<<<g, 256>>>(ybuf, logits, ME);
        }
        k_gemv<<<128, 256>>>(gvec, Wout, bout, gout, CDIM, CDIM);
        k_ln<<<1, 256>>>(gout, gbn, bbn, gcat + (size_t)(3 + b) * CDIM, CDIM);
    }

    // ----- final: LN(concat) @ Wf^T + bf -----
    k_ln<<<1, 256>>>(gcat, gbn2, bbn2, gcatn, 6 * CDIM);
    k_gemv<<<2, 256>>>(gcatn, Wf, bf, (float*)d_out, 10, 6 * CDIM);
}

// round 4
// speedup vs baseline: 2.4372x; 1.1825x over previous
#include <cuda_runtime.h>
#include <cuda_bf16.h>
#include <math.h>
#include <stdint.h>

// Problem constants
#define NV   20000
#define ME   5000
#define EI   160000
#define CDIM 1024
#define HIDD 512

// ---------------- device scratch (static, no allocation) ----------------
__device__ __align__(16) float g_bufA[(size_t)NV * HIDD];
__device__ __align__(16) float g_bufB[(size_t)NV * HIDD];
__device__ __align__(16) float g_bufC[(size_t)NV * CDIM];
__device__ __align__(16) float g_bufD[(size_t)NV * CDIM];
__device__ __align__(16) float g_Y[(size_t)ME * CDIM];
__device__ __align__(16) float g_ybuf[(size_t)ME * CDIM];
__device__ __align__(16) float g_ABy[(size_t)ME * HIDD];
__device__ float g_alpha[ME];
__device__ float g_vm[NV];
__device__ float g_vwinv[NV];
__device__ float g_logits[NV];

__device__ int g_degE[ME], g_eoff[ME + 1], g_ecur[ME];
__device__ int g_degV[NV], g_voff[NV + 1], g_vcur[NV];
__device__ int g_elist[EI];
__device__ int g_vlist[EI];

__device__ __align__(16) float g_Wab[512 * 1024];
__device__ float g_gvec[CDIM];
__device__ float g_gout[CDIM];
__device__ float g_gcat[6 * CDIM];
__device__ float g_gcatn[6 * CDIM];
__device__ unsigned g_menc;
__device__ float g_S;

// bf16 split buffers (16B-aligned for cp.async)
__device__ __align__(16) __nv_bfloat16 g_Acthi[(size_t)NV * CDIM];
__device__ __align__(16) __nv_bfloat16 g_Actlo[(size_t)NV * CDIM];   // also reused as y-hi
__device__ __align__(16) __nv_bfloat16 g_Wt0hi[512 * 1024], g_Wt0lo[512 * 1024];
__device__ __align__(16) __nv_bfloat16 g_Wt1hi[1024 * 512], g_Wt1lo[1024 * 512];
__device__ __align__(16) __nv_bfloat16 g_Wabhi[512 * 1024], g_Wablo[512 * 1024];

// ---------------- helpers ----------------
__device__ __forceinline__ uint32_t smem_u32(const void* p) {
    uint32_t a;
    asm("{ .reg .u64 t; cvta.to.shared.u64 t, %1; cvt.u32.u64 %0, t; }"
        : "=r"(a) : "l"(p));
    return a;
}

__device__ __forceinline__ void cp_cg(uint32_t s, const void* g, int bytes) {
    asm volatile("cp.async.cg.shared.global [%0], [%1], 16, %2;"
                 :: "r"(s), "l"(g), "r"(bytes) : "memory");
}

__device__ __forceinline__ void ldsm4(uint32_t* r, uint32_t addr) {
    asm volatile("ldmatrix.sync.aligned.m8n8.x4.shared.b16 {%0,%1,%2,%3}, [%4];"
                 : "=r"(r[0]), "=r"(r[1]), "=r"(r[2]), "=r"(r[3]) : "r"(addr));
}

__device__ __forceinline__ void mma16816(float* d, const uint32_t* a, const uint32_t* b) {
    asm volatile(
        "mma.sync.aligned.m16n8k16.row.col.f32.bf16.bf16.f32 "
        "{%0,%1,%2,%3}, {%4,%5,%6,%7}, {%8,%9}, {%0,%1,%2,%3};"
        : "+f"(d[0]), "+f"(d[1]), "+f"(d[2]), "+f"(d[3])
        : "r"(a[0]), "r"(a[1]), "r"(a[2]), "r"(a[3]), "r"(b[0]), "r"(b[1]));
}

__device__ __forceinline__ unsigned fenc(float f) {
    unsigned u = __float_as_uint(f);
    return (u & 0x80000000u) ? ~u : (u | 0x80000000u);
}
__device__ __forceinline__ float fdec(unsigned e) {
    unsigned u = (e & 0x80000000u) ? (e & 0x7FFFFFFFu) : ~e;
    return __uint_as_float(u);
}

// ---------------- fp32 -> bf16 hi/lo split ----------------
__global__ void __launch_bounds__(256)
k_split(const float* __restrict__ src, __nv_bfloat16* __restrict__ hi,
        __nv_bfloat16* __restrict__ lo, int n4) {
    int i = blockIdx.x * blockDim.x + threadIdx.x;
    if (i >= n4) return;
    float4 v = ((const float4*)src)[i];
    __nv_bfloat16 h[4], l[4];
    float x[4] = {v.x, v.y, v.z, v.w};
#pragma unroll
    for (int j = 0; j < 4; ++j) {
        h[j] = __float2bfloat16(x[j]);
        l[j] = __float2bfloat16(x[j] - __bfloat162float(h[j]));
    }
    ((__nv_bfloat162*)hi)[2 * i]     = __nv_bfloat162(h[0], h[1]);
    ((__nv_bfloat162*)hi)[2 * i + 1] = __nv_bfloat162(h[2], h[3]);
    ((__nv_bfloat162*)lo)[2 * i]     = __nv_bfloat162(l[0], l[1]);
    ((__nv_bfloat162*)lo)[2 * i + 1] = __nv_bfloat162(l[2], l[3]);
}

// ---------------- bf16 tensor-core GEMM: C = A @ B^T + bias ----------------
// S3=true: 3-pass Ootomo split (hi/lo), S3=false: single-pass hi only.
// Tile 128x128x32, 256 threads, 8 warps (4 along M x 2 along N), warp 32x64.
template <bool S3>
__global__ void __launch_bounds__(256, 1)
k_mma_gemm(const __nv_bfloat16* __restrict__ Ahi, const __nv_bfloat16* __restrict__ Alo,
           const __nv_bfloat16* __restrict__ Bhi, const __nv_bfloat16* __restrict__ Blo,
           const float* __restrict__ bias, float* __restrict__ C,
           int M, int N, int K) {
    extern __shared__ char smraw[];
    uint32_t sb = smem_u32(smraw);
    constexpr int OFF_AL = 10240;
    constexpr int OFF_BH = S3 ? 20480 : 10240;
    constexpr int OFF_BL = 30720;
    constexpr int STG = S3 ? 40960 : 20480;
    int tid = threadIdx.x, lane = tid & 31, warp = tid >> 5;
    int wm = (warp & 3) * 32;
    int wn = (warp >> 2) * 64;
    int bm = blockIdx.y * 128, bn = blockIdx.x * 128;

    float acc[2][8][4];
#pragma unroll
    for (int a = 0; a < 2; ++a)
#pragma unroll
        for (int b = 0; b < 8; ++b)
#pragma unroll
            for (int c = 0; c < 4; ++c) acc[a][b][c] = 0.f;

    auto issue = [&](int kt, int s) {
        int k0 = kt * 32;
        uint32_t sbase = sb + s * STG;
#pragma unroll
        for (int i = 0; i < 2; ++i) {
            int idx = i * 256 + tid;
            int row = idx >> 2, c = idx & 3;
            uint32_t soff = sbase + row * 80 + c * 16;
            int ar = bm + row;
            int pa = (ar < M) ? 16 : 0;
            int arc = (ar < M) ? ar : 0;
            cp_cg(soff,          Ahi + (size_t)arc * K + k0 + c * 8, pa);
            cp_cg(soff + OFF_BH, Bhi + (size_t)(bn + row) * K + k0 + c * 8, 16);
            if (S3) {
                cp_cg(soff + OFF_AL, Alo + (size_t)arc * K + k0 + c * 8, pa);
                cp_cg(soff + OFF_BL, Blo + (size_t)(bn + row) * K + k0 + c * 8, 16);
            }
        }
        asm volatile("cp.async.commit_group;" ::: "memory");
    };

    int KT = K / 32;
    issue(0, 0);
    for (int kt = 0; kt < KT; ++kt) {
        int s = kt & 1;
        if (kt + 1 < KT) {
            issue(kt + 1, s ^ 1);
            asm volatile("cp.async.wait_group 1;" ::: "memory");
        } else {
            asm volatile("cp.async.wait_group 0;" ::: "memory");
        }
        __syncthreads();
        uint32_t sbase = sb + s * STG;
#pragma unroll
        for (int kk = 0; kk < 2; ++kk) {
            uint32_t ah[2][4], al[2][4];
#pragma unroll
            for (int mt = 0; mt < 2; ++mt) {
                uint32_t addr = sbase + (uint32_t)(wm + mt * 16 + (lane & 15)) * 80
                              + kk * 32 + (lane >> 4) * 16;
                ldsm4(ah[mt], addr);
                if (S3) ldsm4(al[mt], addr + OFF_AL);
            }
            uint32_t bh[8][2], bl[8][2];
#pragma unroll
            for (int np = 0; np < 4; ++np) {
                int row = wn + np * 16 + (lane & 7) + ((lane >> 4) << 3);
                uint32_t addr = sbase + OFF_BH + (uint32_t)row * 80
                              + kk * 32 + ((lane >> 3) & 1) * 16;
                uint32_t t[4];
                ldsm4(t, addr);
                bh[np * 2][0] = t[0]; bh[np * 2][1] = t[1];
                bh[np * 2 + 1][0] = t[2]; bh[np * 2 + 1][1] = t[3];
                if (S3) {
                    ldsm4(t, addr + (OFF_BL - OFF_BH));
                    bl[np * 2][0] = t[0]; bl[np * 2][1] = t[1];
                    bl[np * 2 + 1][0] = t[2]; bl[np * 2 + 1][1] = t[3];
                }
            }
#pragma unroll
            for (int mt = 0; mt < 2; ++mt)
#pragma unroll
                for (int nt = 0; nt < 8; ++nt) {
                    mma16816(acc[mt][nt], ah[mt], bh[nt]);
                    if (S3) {
                        mma16816(acc[mt][nt], ah[mt], bl[nt]);
                        mma16816(acc[mt][nt], al[mt], bh[nt]);
                    }
                }
        }
        __syncthreads();
    }

    // epilogue: direct register -> GMEM
#pragma unroll
    for (int mt = 0; mt < 2; ++mt) {
        int r0 = bm + wm + mt * 16 + (lane >> 2);
#pragma unroll
        for (int nt = 0; nt < 8; ++nt) {
            int c0 = bn + wn + nt * 8 + (lane & 3) * 2;
            float bx = bias ? __ldg(bias + c0) : 0.f;
            float by = bias ? __ldg(bias + c0 + 1) : 0.f;
            if (r0 < M) {
                float2 v = make_float2(acc[mt][nt][0] + bx, acc[mt][nt][1] + by);
                *(float2*)(C + (size_t)r0 * N + c0) = v;
            }
            if (r0 + 8 < M) {
                float2 v = make_float2(acc[mt][nt][2] + bx, acc[mt][nt][3] + by);
                *(float2*)(C + (size_t)(r0 + 8) * N + c0) = v;
            }
        }
    }
}

// ---------------- CSR construction ----------------
__global__ void k_zero_csr() {
    int i = blockIdx.x * blockDim.x + threadIdx.x;
    if (i < ME) g_degE[i] = 0;
    if (i < NV) g_degV[i] = 0;
}

__global__ void k_count(const int* __restrict__ vi, const int* __restrict__ ei) {
    int i = blockIdx.x * blockDim.x + threadIdx.x;
    if (i < EI) {
        atomicAdd(&g_degV[vi[i]], 1);
        atomicAdd(&g_degE[ei[i]], 1);
    }
}

__global__ void __launch_bounds__(1024)
k_scan(const int* __restrict__ cnt, int* __restrict__ off,
       int* __restrict__ cur, int n) {
    __shared__ int wsum[32];
    int tid = threadIdx.x, lane = tid & 31, w = tid >> 5;
    int chunk = (n + 1023) / 1024;
    int beg = min(tid * chunk, n);
    int end = min(beg + chunk, n);
    int s = 0;
    for (int i = beg; i < end; ++i) s += cnt[i];
    int v = s;
#pragma unroll
    for (int o = 1; o < 32; o <<= 1) {
        int u = __shfl_up_sync(0xffffffffu, v, o);
        if (lane >= o) v += u;
    }
    if (lane == 31) wsum[w] = v;
    __syncthreads();
    if (w == 0) {
        int ws = wsum[lane];
#pragma unroll
        for (int o = 1; o < 32; o <<= 1) {
            int u = __shfl_up_sync(0xffffffffu, ws, o);
            if (lane >= o) ws += u;
        }
        wsum[lane] = ws;
    }
    __syncthreads();
    int excl = v - s + (w > 0 ? wsum[w - 1] : 0);
    int run = excl;
    for (int i = beg; i < end; ++i) { off[i] = run; cur[i] = run; run += cnt[i]; }
    if (tid == 1023) off[n] = wsum[31];
}

__global__ void k_fill(const int* __restrict__ vi, const int* __restrict__ ei) {
    int i = blockIdx.x * blockDim.x + threadIdx.x;
    if (i < EI) {
        int v = vi[i], e = ei[i];
        g_elist[atomicAdd(&g_ecur[e], 1)] = v;
        g_vlist[atomicAdd(&g_vcur[v], 1)] = e;
    }
}

// ---------------- v2e mean (+ edge logit / + bf16 hi emission) -------------
template <int D, bool WE>
__global__ void __launch_bounds__(D / 4)
k_v2e(const float* __restrict__ Hp, const float* __restrict__ we,
      float* __restrict__ Y, float* __restrict__ alpha,
      __nv_bfloat16* __restrict__ Yhi) {
    constexpr int T = D / 4;
    int e = blockIdx.x;
    int beg = g_eoff[e], end = g_eoff[e + 1];
    int t = threadIdx.x;
    float4 acc = make_float4(0.f, 0.f, 0.f, 0.f);
    for (int i = beg; i < end; ++i) {
        const float4* row = (const float4*)(Hp + (size_t)g_elist[i] * D);
        float4 v = row[t];
        acc.x += v.x; acc.y += v.y; acc.z += v.z; acc.w += v.w;
    }
    float inv = 1.f / fmaxf((float)(end - beg), 1.f);
    float4 y = make_float4(acc.x * inv, acc.y * inv, acc.z * inv, acc.w * inv);
    ((float4*)(Y + (size_t)e * D))[t] = y;
    if (Yhi) {
        __nv_bfloat162* ph = (__nv_bfloat162*)(Yhi + (size_t)e * D);
        ph[2 * t]     = __nv_bfloat162(__float2bfloat16(y.x), __float2bfloat16(y.y));
        ph[2 * t + 1] = __nv_bfloat162(__float2bfloat16(y.z), __float2bfloat16(y.w));
    }
    if (WE) {
        float4 w4 = ((const float4*)we)[t];
        float dot = y.x * w4.x + y.y * w4.y + y.z * w4.z + y.w * w4.w;
        __shared__ float red[T];
        red[t] = dot;
        __syncthreads();
        for (int s = T / 2; s > 0; s >>= 1) {
            if (t < s) red[t] += red[t + s];
            __syncthreads();
        }
        if (t == 0) alpha[e] = red[0];
    }
}

// ---------------- per-vertex softmax stats over incident edges -------------
__global__ void k_vstats() {
    int v = blockIdx.x * blockDim.x + threadIdx.x;
    if (v >= NV) return;
    int beg = g_voff[v], end = g_voff[v + 1];
    float m = -INFINITY;
    for (int t = beg; t < end; ++t) {
        float a = g_alpha[g_vlist[t]];
        a = a > 0.f ? a : 0.2f * a;
        m = fmaxf(m, a);
    }
    float s = 0.f;
    for (int t = beg; t < end; ++t) {
        float a = g_alpha[g_vlist[t]];
        a = a > 0.f ? a : 0.2f * a;
        s += expf(a - m);
    }
    g_vm[v] = m;
    g_vwinv[v] = 1.f / (s + 1e-12f);
}

// ---------------- e2v: softmax-weighted sum (+ bf16 hi/lo emission) --------
template <int D, bool ELU>
__global__ void __launch_bounds__(D / 4)
k_e2v(const float* __restrict__ Y, float* __restrict__ Xo,
      __nv_bfloat16* __restrict__ Xhi, __nv_bfloat16* __restrict__ Xlo) {
    int v = blockIdx.x;
    int beg = g_voff[v], end = g_voff[v + 1];
    int t = threadIdx.x;
    float4 acc = make_float4(0.f, 0.f, 0.f, 0.f);
    float m = g_vm[v], winv = g_vwinv[v];
    for (int i = beg; i < end; ++i) {
        int e = g_vlist[i];
        float a = g_alpha[e];
        a = a > 0.f ? a : 0.2f * a;
        float w = expf(a - m) * winv;
        float4 yv = ((const float4*)(Y + (size_t)e * D))[t];
        acc.x += w * yv.x; acc.y += w * yv.y; acc.z += w * yv.z; acc.w += w * yv.w;
    }
    if (ELU) {
        acc.x = acc.x > 0.f ? acc.x : expm1f(acc.x);
        acc.y = acc.y > 0.f ? acc.y : expm1f(acc.y);
        acc.z = acc.z > 0.f ? acc.z : expm1f(acc.z);
        acc.w = acc.w > 0.f ? acc.w : expm1f(acc.w);
    }
    ((float4*)(Xo + (size_t)v * D))[t] = acc;
    if (Xhi) {
        float x[4] = {acc.x, acc.y, acc.z, acc.w};
        __nv_bfloat16 h[4];
#pragma unroll
        for (int j = 0; j < 4; ++j) h[j] = __float2bfloat16(x[j]);
        __nv_bfloat162* ph = (__nv_bfloat162*)(Xhi + (size_t)v * D);
        ph[2 * t]     = __nv_bfloat162(h[0], h[1]);
        ph[2 * t + 1] = __nv_bfloat162(h[2], h[3]);
        if (Xlo) {
            __nv_bfloat16 l[4];
#pragma unroll
            for (int j = 0; j < 4; ++j)
                l[j] = __float2bfloat16(x[j] - __bfloat162float(h[j]));
            __nv_bfloat162* pl = (__nv_bfloat162*)(Xlo + (size_t)v * D);
            pl[2 * t]     = __nv_bfloat162(l[0], l[1]);
            pl[2 * t + 1] = __nv_bfloat162(l[2], l[3]);
        }
    }
}

// ---------------- gated attention pieces ----------------
__global__ void __launch_bounds__(256)
k_logits(const float* __restrict__ AB, const float* __restrict__ ba,
         const float* __restrict__ bb, const float* __restrict__ Wc,
         const float* __restrict__ bc, float* __restrict__ logit) {
    int r = blockIdx.x, j = threadIdx.x;
    float av = tanhf(AB[(size_t)r * 512 + j] + ba[j]);
    float bv = AB[(size_t)r * 512 + 256 + j] + bb[j];
    float sg = 1.f / (1.f + expf(-bv));
    float v = av * sg * Wc[j];
    __shared__ float red[256];
    red[j] = v;
    __syncthreads();
    for (int s = 128; s > 0; s >>= 1) {
        if (j < s) red[j] += red[j + s];
        __syncthreads();
    }
    if (j == 0) logit[r] = red[0] + bc[0];
}

__global__ void k_attn_init() {
    int i = blockIdx.x * blockDim.x + threadIdx.x;
    if (i < CDIM) g_gvec[i] = 0.f;
    if (i == 0) { g_menc = 0u; g_S = 0.f; }
}

__global__ void __launch_bounds__(256)
k_maxred(const float* __restrict__ l, int n) {
    float m = -INFINITY;
    for (int i = blockIdx.x * blockDim.x + threadIdx.x; i < n; i += gridDim.x * blockDim.x)
        m = fmaxf(m, l[i]);
    __shared__ float red[256];
    red[threadIdx.x] = m;
    __syncthreads();
    for (int s = 128; s > 0; s >>= 1) {
        if (threadIdx.x < s) red[threadIdx.x] = fmaxf(red[threadIdx.x], red[threadIdx.x + s]);
        __syncthreads();
    }
    if (threadIdx.x == 0) atomicMax(&g_menc, fenc(red[0]));
}

__global__ void __launch_bounds__(256)
k_sumexp(const float* __restrict__ l, int n) {
    float m = fdec(g_menc);
    float s = 0.f;
    for (int i = blockIdx.x * blockDim.x + threadIdx.x; i < n; i += gridDim.x * blockDim.x)
        s += expf(l[i] - m);
    __shared__ float red[256];
    red[threadIdx.x] = s;
    __syncthreads();
    for (int st = 128; st > 0; st >>= 1) {
        if (threadIdx.x < st) red[threadIdx.x] += red[threadIdx.x + st];
        __syncthreads();
    }
    if (threadIdx.x == 0) atomicAdd(&g_S, red[0]);
}

__global__ void __launch_bounds__(256)
k_wsum(const float* __restrict__ x, const float* __restrict__ l, int n) {
    int c = blockIdx.x * 256 + threadIdx.x;
    float m = fdec(g_menc);
    float invS = 1.f / g_S;
    float acc = 0.f;
    for (int r = blockIdx.y; r < n; r += gridDim.y)
        acc += expf(l[r] - m) * invS * x[(size_t)r * CDIM + c];
    atomicAdd(&g_gvec[c], acc);
}

__global__ void k_gemv(const float* __restrict__ v, const float* __restrict__ W,
                       const float* __restrict__ b, float* __restrict__ out,
                       int R, int K) {
    int row = blockIdx.x * (blockDim.x >> 5) + (threadIdx.x >> 5);
    if (row >= R) return;
    int lane = threadIdx.x & 31;
    const float* wr = W + (size_t)row * K;
    float s = 0.f;
    for (int k = lane; k < K; k += 32) s += v[k] * wr[k];
    for (int o = 16; o; o >>= 1) s += __shfl_down_sync(0xffffffffu, s, o);
    if (lane == 0) out[row] = s + b[row];
}

__global__ void __launch_bounds__(256)
k_ln(const float* __restrict__ x, const float* __restrict__ g,
     const float* __restrict__ b, float* __restrict__ out, int D) {
    __shared__ float red[256];
    __shared__ float mu_s, rstd_s;
    float s = 0.f;
    for (int i = threadIdx.x; i < D; i += 256) s += x[i];
    red[threadIdx.x] = s;
    __syncthreads();
    for (int st = 128; st > 0; st >>= 1) {
        if (threadIdx.x < st) red[threadIdx.x] += red[threadIdx.x + st];
        __syncthreads();
    }
    if (threadIdx.x == 0) mu_s = red[0] / (float)D;
    __syncthreads();
    float mu = mu_s;
    float vs = 0.f;
    for (int i = threadIdx.x; i < D; i += 256) {
        float d = x[i] - mu;
        vs += d * d;
    }
    red[threadIdx.x] = vs;
    __syncthreads();
    for (int st = 128; st > 0; st >>= 1) {
        if (threadIdx.x < st) red[threadIdx.x] += red[threadIdx.x + st];
        __syncthreads();
    }
    if (threadIdx.x == 0) rstd_s = rsqrtf(red[0] / (float)D + 1e-5f);
    __syncthreads();
    float rstd = rstd_s;
    for (int i = threadIdx.x; i < D; i += 256)
        out[i] = (x[i] - mu) * rstd * g[i] + b[i];
}

// ---------------- host orchestration ----------------
extern "C" void kernel_launch(void* const* d_in, const int* in_sizes, int n_in,
                              void* d_out, int out_size) {
    float *bufA, *bufB, *bufC, *bufD, *Y, *ybuf, *ABy, *alpha, *logits;
    float *Wab, *gvec, *gout, *gcat, *gcatn;
    int *degE, *degV, *eoff, *voff, *ecur, *vcur;
    __nv_bfloat16 *Acthi, *Actlo, *Wt0hi, *Wt0lo, *Wt1hi, *Wt1lo, *Wabhi, *Wablo;
    cudaGetSymbolAddress((void**)&bufA, g_bufA);
    cudaGetSymbolAddress((void**)&bufB, g_bufB);
    cudaGetSymbolAddress((void**)&bufC, g_bufC);
    cudaGetSymbolAddress((void**)&bufD, g_bufD);
    cudaGetSymbolAddress((void**)&Y, g_Y);
    cudaGetSymbolAddress((void**)&ybuf, g_ybuf);
    cudaGetSymbolAddress((void**)&ABy, g_ABy);
    cudaGetSymbolAddress((void**)&alpha, g_alpha);
    cudaGetSymbolAddress((void**)&logits, g_logits);
    cudaGetSymbolAddress((void**)&Wab, g_Wab);
    cudaGetSymbolAddress((void**)&gvec, g_gvec);
    cudaGetSymbolAddress((void**)&gout, g_gout);
    cudaGetSymbolAddress((void**)&gcat, g_gcat);
    cudaGetSymbolAddress((void**)&gcatn, g_gcatn);
    cudaGetSymbolAddress((void**)&degE, g_degE);
    cudaGetSymbolAddress((void**)&degV, g_degV);
    cudaGetSymbolAddress((void**)&eoff, g_eoff);
    cudaGetSymbolAddress((void**)&voff, g_voff);
    cudaGetSymbolAddress((void**)&ecur, g_ecur);
    cudaGetSymbolAddress((void**)&vcur, g_vcur);
    cudaGetSymbolAddress((void**)&Acthi, g_Acthi);
    cudaGetSymbolAddress((void**)&Actlo, g_Actlo);
    cudaGetSymbolAddress((void**)&Wt0hi, g_Wt0hi);
    cudaGetSymbolAddress((void**)&Wt0lo, g_Wt0lo);
    cudaGetSymbolAddress((void**)&Wt1hi, g_Wt1hi);
    cudaGetSymbolAddress((void**)&Wt1lo, g_Wt1lo);
    cudaGetSymbolAddress((void**)&Wabhi, g_Wabhi);
    cudaGetSymbolAddress((void**)&Wablo, g_Wablo);

    const int GSMEM3 = 81920, GSMEM1 = 40960;
    cudaFuncSetAttribute(k_mma_gemm<true>, cudaFuncAttributeMaxDynamicSharedMemorySize, GSMEM3);
    cudaFuncSetAttribute(k_mma_gemm<false>, cudaFuncAttributeMaxDynamicSharedMemorySize, GSMEM1);

    // input index map (signature vs dict order)
    int xi[3], vii[3], eii[3];
    if (in_sizes[1] == NV * CDIM) {
        for (int b = 0; b < 3; ++b) { xi[b] = b; vii[b] = 3 + 2 * b; eii[b] = 4 + 2 * b; }
    } else {
        for (int b = 0; b < 3; ++b) { xi[b] = 3 * b; vii[b] = 3 * b + 1; eii[b] = 3 * b + 2; }
    }
    const float* Wt0  = (const float*)d_in[9];
    const float* bt0  = (const float*)d_in[10];
    const float* we0  = (const float*)d_in[11];
    const float* Wt1  = (const float*)d_in[12];
    const float* bt1  = (const float*)d_in[13];
    const float* we1  = (const float*)d_in[14];
    const float* Wa   = (const float*)d_in[15];
    const float* ba   = (const float*)d_in[16];
    const float* Wb   = (const float*)d_in[17];
    const float* bb   = (const float*)d_in[18];
    const float* Wc   = (const float*)d_in[19];
    const float* bc   = (const float*)d_in[20];
    const float* Wout = (const float*)d_in[21];
    const float* bout = (const float*)d_in[22];
    const float* gbn  = (const float*)d_in[23];
    const float* bbn  = (const float*)d_in[24];
    const float* gbn2 = (const float*)d_in[25];
    const float* bbn2 = (const float*)d_in[26];
    const float* Wf   = (const float*)d_in[27];
    const float* bf   = (const float*)d_in[28];

    const __nv_bfloat16* nbf = nullptr;
    const int EB = (EI + 255) / 256;

    // launches 1-2: assemble [Wa;Wb]
    cudaMemcpyAsync(Wab, Wa, (size_t)256 * 1024 * sizeof(float), cudaMemcpyDeviceToDevice, 0);
    cudaMemcpyAsync(Wab + 256 * 1024, Wb, (size_t)256 * 1024 * sizeof(float), cudaMemcpyDeviceToDevice, 0);
    // launches 3-5: splits needed for GEMM1 (+Wab for later) — GEMM1 lands at launch 6
    k_split<<<(NV * CDIM / 4 + 255) / 256, 256>>>((const float*)d_in[xi[0]], Acthi, Actlo, NV * CDIM / 4);
    k_split<<<512, 256>>>(Wt0, Wt0hi, Wt0lo, 512 * 1024 / 4);
    k_split<<<512, 256>>>(Wab, Wabhi, Wablo, 512 * 1024 / 4);

    for (int b = 0; b < 3; ++b) {
        const float* X = (const float*)d_in[xi[b]];
        const int* vi = (const int*)d_in[vii[b]];
        const int* ei = (const int*)d_in[eii[b]];

        if (b > 0)
            k_split<<<(NV * CDIM / 4 + 255) / 256, 256>>>(X, Acthi, Actlo, NV * CDIM / 4);

        // ----- layer 1 GEMM (C -> HID) — launch #6 on b==0, profiled by ncu -----
        {
            dim3 g(HIDD / 128, (NV + 127) / 128);
            k_mma_gemm<true><<<g, 256, GSMEM3>>>(Acthi, Actlo, Wt0hi, Wt0lo, bt0, bufA, NV, HIDD, CDIM);
        }
        if (b == 0)
            k_split<<<512, 256>>>(Wt1, Wt1hi, Wt1lo, 1024 * 512 / 4);

        // ----- CSR -----
        k_zero_csr<<<(NV + 255) / 256, 256>>>();
        k_count<<<EB, 256>>>(vi, ei);
        k_scan<<<1, 1024>>>(degE, eoff, ecur, ME);
        k_scan<<<1, 1024>>>(degV, voff, vcur, NV);
        k_fill<<<EB, 256>>>(vi, ei);

        // ----- layer 1 aggregation (elu), emit bf16 hi/lo for layer-2 GEMM -----
        k_v2e<HIDD, true><<<ME, HIDD / 4>>>(bufA, we0, Y, alpha, nullptr);
        k_vstats<<<(NV + 255) / 256, 256>>>();
        k_e2v<HIDD, true><<<NV, HIDD / 4>>>(Y, bufB, Acthi, Actlo);

        // ----- layer 2 (HID -> C, no elu) -----
        {
            dim3 g(CDIM / 128, (NV + 127) / 128);
            k_mma_gemm<true><<<g, 256, GSMEM3>>>(Acthi, Actlo, Wt1hi, Wt1lo, bt1, bufC, NV, CDIM, HIDD);
        }
        k_v2e<CDIM, true><<<ME, CDIM / 4>>>(bufC, we1, Y, alpha, nullptr);
        k_vstats<<<(NV + 255) / 256, 256>>>();
        // h: fp32 + bf16 hi (single-pass attention GEMM needs hi only)
        k_e2v<CDIM, false><<<NV, CDIM / 4>>>(Y, bufD, Acthi, nullptr);

        // ----- y = v2e_mean(h): fp32 + bf16 hi (into Actlo region) -----
        k_v2e<CDIM, false><<<ME, CDIM / 4>>>(bufD, nullptr, ybuf, alpha, Actlo);

        // ----- gated attention on h (20000 rows), single-pass bf16 -----
        {
            dim3 g(512 / 128, (NV + 127) / 128);
            k_mma_gemm<false><<<g, 256, GSMEM1>>>(Acthi, nbf, Wabhi, nbf,
                                                  (const float*)nullptr, bufA, NV, 512, CDIM);
        }
        k_logits<<<NV, 256>>>(bufA, ba, bb, Wc, bc, logits);
        k_attn_init<<<4, 256>>>();
        k_maxred<<<40, 256>>>(logits, NV);
        k_sumexp<<<40, 256>>>(logits, NV);
        {
            dim3 g(CDIM / 256, 125);
            k_wsum<<<g, 256>>>(bufD, logits, NV);
        }
        k_gemv<<<128, 256>>>(gvec, Wout, bout, gout, CDIM, CDIM);
        k_ln<<<1, 256>>>(gout, gbn, bbn, gcat + (size_t)b * CDIM, CDIM);

        // ----- gated attention on y (5000 rows), single-pass bf16 -----
        {
            dim3 g(512 / 128, (ME + 127) / 128);
            k_mma_gemm<false><<<g, 256, GSMEM1>>>(Actlo, nbf, Wabhi, nbf,
                                                  (const float*)nullptr, ABy, ME, 512, CDIM);
        }
        k_logits<<<ME, 256>>>(ABy, ba, bb, Wc, bc, logits);
        k_attn_init<<<4, 256>>>();
        k_maxred<<<20, 256>>>(logits, ME);
        k_sumexp<<<20, 256>>>(logits, ME);
        {
            dim3 g(CDIM / 256, 125);
            k_wsum<<<g, 256>>>(ybuf, logits, ME);
        }
        k_gemv<<<128, 256>>>(gvec, Wout, bout, gout, CDIM, CDIM);
        k_ln<<<1, 256>>>(gout, gbn, bbn, gcat + (size_t)(3 + b) * CDIM, CDIM);
    }

    // ----- final: LN(concat) @ Wf^T + bf -----
    k_ln<<<1, 256>>>(gcat, gbn2, bbn2, gcatn, 6 * CDIM);
    k_gemv<<<2, 256>>>(gcatn, Wf, bf, (float*)d_out, 10, 6 * CDIM);
}

// round 5
// speedup vs baseline: 2.7941x; 1.1464x over previous
#include <cuda_runtime.h>
#include <cuda_bf16.h>
#include <math.h>
#include <stdint.h>

// Problem constants
#define NV   20000
#define ME   5000
#define EI   160000
#define CDIM 1024
#define HIDD 512

// ---------------- device scratch (static, no allocation) ----------------
__device__ __align__(16) float g_bufA[(size_t)NV * HIDD];
__device__ __align__(16) float g_bufB[(size_t)NV * HIDD];
__device__ __align__(16) float g_bufC[(size_t)NV * CDIM];
__device__ __align__(16) float g_bufD[(size_t)NV * CDIM];
__device__ __align__(16) float g_Y[(size_t)ME * CDIM];
__device__ __align__(16) float g_ybuf[(size_t)ME * CDIM];
__device__ __align__(16) float g_ABy[(size_t)ME * HIDD];
__device__ float g_alpha[ME];
__device__ float g_vm[NV];
__device__ float g_vwinv[NV];
__device__ float g_logits[NV];

__device__ int g_degE[ME], g_eoff[ME + 1], g_ecur[ME];
__device__ int g_degV[NV], g_voff[NV + 1], g_vcur[NV];
__device__ int g_elist[EI];
__device__ int g_vlist[EI];

__device__ __align__(16) float g_Wab[512 * 1024];
__device__ float g_gvec[CDIM];
__device__ float g_gout[CDIM];
__device__ float g_gcat[6 * CDIM];
__device__ float g_gcatn[6 * CDIM];
__device__ unsigned g_menc;
__device__ float g_S;

// bf16 split buffers (16B-aligned for cp.async)
__device__ __align__(16) __nv_bfloat16 g_Acthi[(size_t)NV * CDIM];
__device__ __align__(16) __nv_bfloat16 g_Actlo[(size_t)NV * CDIM];   // also reused as y-hi
__device__ __align__(16) __nv_bfloat16 g_Wt0hi[512 * 1024], g_Wt0lo[512 * 1024];
__device__ __align__(16) __nv_bfloat16 g_Wt1hi[1024 * 512], g_Wt1lo[1024 * 512];
__device__ __align__(16) __nv_bfloat16 g_Wabhi[512 * 1024], g_Wablo[512 * 1024];

// ---------------- helpers ----------------
__device__ __forceinline__ uint32_t smem_u32(const void* p) {
    uint32_t a;
    asm("{ .reg .u64 t; cvta.to.shared.u64 t, %1; cvt.u32.u64 %0, t; }"
        : "=r"(a) : "l"(p));
    return a;
}

__device__ __forceinline__ void cp_cg(uint32_t s, const void* g, int bytes) {
    asm volatile("cp.async.cg.shared.global [%0], [%1], 16, %2;"
                 :: "r"(s), "l"(g), "r"(bytes) : "memory");
}

__device__ __forceinline__ void ldsm4(uint32_t* r, uint32_t addr) {
    asm volatile("ldmatrix.sync.aligned.m8n8.x4.shared.b16 {%0,%1,%2,%3}, [%4];"
                 : "=r"(r[0]), "=r"(r[1]), "=r"(r[2]), "=r"(r[3]) : "r"(addr));
}

__device__ __forceinline__ void mma16816(float* d, const uint32_t* a, const uint32_t* b) {
    asm volatile(
        "mma.sync.aligned.m16n8k16.row.col.f32.bf16.bf16.f32 "
        "{%0,%1,%2,%3}, {%4,%5,%6,%7}, {%8,%9}, {%0,%1,%2,%3};"
        : "+f"(d[0]), "+f"(d[1]), "+f"(d[2]), "+f"(d[3])
        : "r"(a[0]), "r"(a[1]), "r"(a[2]), "r"(a[3]), "r"(b[0]), "r"(b[1]));
}

__device__ __forceinline__ unsigned fenc(float f) {
    unsigned u = __float_as_uint(f);
    return (u & 0x80000000u) ? ~u : (u | 0x80000000u);
}
__device__ __forceinline__ float fdec(unsigned e) {
    unsigned u = (e & 0x80000000u) ? (e & 0x7FFFFFFFu) : ~e;
    return __uint_as_float(u);
}

// ---------------- fp32 -> bf16 hi/lo split ----------------
__global__ void __launch_bounds__(256)
k_split(const float* __restrict__ src, __nv_bfloat16* __restrict__ hi,
        __nv_bfloat16* __restrict__ lo, int n4) {
    int i = blockIdx.x * blockDim.x + threadIdx.x;
    if (i >= n4) return;
    float4 v = ((const float4*)src)[i];
    __nv_bfloat16 h[4], l[4];
    float x[4] = {v.x, v.y, v.z, v.w};
#pragma unroll
    for (int j = 0; j < 4; ++j) {
        h[j] = __float2bfloat16(x[j]);
        l[j] = __float2bfloat16(x[j] - __bfloat162float(h[j]));
    }
    ((__nv_bfloat162*)hi)[2 * i]     = __nv_bfloat162(h[0], h[1]);
    ((__nv_bfloat162*)hi)[2 * i + 1] = __nv_bfloat162(h[2], h[3]);
    ((__nv_bfloat162*)lo)[2 * i]     = __nv_bfloat162(l[0], l[1]);
    ((__nv_bfloat162*)lo)[2 * i + 1] = __nv_bfloat162(l[2], l[3]);
}

// ---------------- bf16 tensor-core GEMM: C = A @ B^T + bias ----------------
// S3=true: 3-pass Ootomo split (hi/lo), S3=false: single-pass hi only.
// Tile 128x128x32, 256 threads, 8 warps (4 along M x 2 along N), warp 32x64.
// Register-lean B-fragment streaming -> <=128 regs -> 2 CTAs/SM.
template <bool S3>
__global__ void __launch_bounds__(256, 2)
k_mma_gemm(const __nv_bfloat16* __restrict__ Ahi, const __nv_bfloat16* __restrict__ Alo,
           const __nv_bfloat16* __restrict__ Bhi, const __nv_bfloat16* __restrict__ Blo,
           const float* __restrict__ bias, float* __restrict__ C,
           int M, int N, int K) {
    extern __shared__ char smraw[];
    uint32_t sb = smem_u32(smraw);
    constexpr int OFF_AL = 10240;
    constexpr int OFF_BH = S3 ? 20480 : 10240;
    constexpr int OFF_BL = 30720;
    constexpr int STG = S3 ? 40960 : 20480;
    int tid = threadIdx.x, lane = tid & 31, warp = tid >> 5;
    int wm = (warp & 3) * 32;
    int wn = (warp >> 2) * 64;
    int bm = blockIdx.y * 128, bn = blockIdx.x * 128;

    float acc[2][8][4];
#pragma unroll
    for (int a = 0; a < 2; ++a)
#pragma unroll
        for (int b = 0; b < 8; ++b)
#pragma unroll
            for (int c = 0; c < 4; ++c) acc[a][b][c] = 0.f;

    auto issue = [&](int kt, int s) {
        int k0 = kt * 32;
        uint32_t sbase = sb + s * STG;
#pragma unroll
        for (int i = 0; i < 2; ++i) {
            int idx = i * 256 + tid;
            int row = idx >> 2, c = idx & 3;
            uint32_t soff = sbase + row * 80 + c * 16;
            int ar = bm + row;
            int pa = (ar < M) ? 16 : 0;
            int arc = (ar < M) ? ar : 0;
            cp_cg(soff,          Ahi + (size_t)arc * K + k0 + c * 8, pa);
            cp_cg(soff + OFF_BH, Bhi + (size_t)(bn + row) * K + k0 + c * 8, 16);
            if (S3) {
                cp_cg(soff + OFF_AL, Alo + (size_t)arc * K + k0 + c * 8, pa);
                cp_cg(soff + OFF_BL, Blo + (size_t)(bn + row) * K + k0 + c * 8, 16);
            }
        }
        asm volatile("cp.async.commit_group;" ::: "memory");
    };

    int KT = K / 32;
    issue(0, 0);
    for (int kt = 0; kt < KT; ++kt) {
        int s = kt & 1;
        if (kt + 1 < KT) {
            issue(kt + 1, s ^ 1);
            asm volatile("cp.async.wait_group 1;" ::: "memory");
        } else {
            asm volatile("cp.async.wait_group 0;" ::: "memory");
        }
        __syncthreads();
        uint32_t sbase = sb + s * STG;
#pragma unroll
        for (int kk = 0; kk < 2; ++kk) {
            uint32_t ah[2][4], al[2][4];
#pragma unroll
            for (int mt = 0; mt < 2; ++mt) {
                uint32_t addr = sbase + (uint32_t)(wm + mt * 16 + (lane & 15)) * 80
                              + kk * 32 + (lane >> 4) * 16;
                ldsm4(ah[mt], addr);
                if (S3) ldsm4(al[mt], addr + OFF_AL);
            }
            // stream B fragments: load one x4 pair, consume immediately
#pragma unroll
            for (int np = 0; np < 4; ++np) {
                int row = wn + np * 16 + (lane & 7) + ((lane >> 4) << 3);
                uint32_t addr = sbase + OFF_BH + (uint32_t)row * 80
                              + kk * 32 + ((lane >> 3) & 1) * 16;
                uint32_t tb[4];
                ldsm4(tb, addr);
#pragma unroll
                for (int mt = 0; mt < 2; ++mt) {
                    mma16816(acc[mt][2 * np],     ah[mt], tb);
                    mma16816(acc[mt][2 * np + 1], ah[mt], tb + 2);
                }
                if (S3) {
                    uint32_t tl[4];
                    ldsm4(tl, addr + (OFF_BL - OFF_BH));
#pragma unroll
                    for (int mt = 0; mt < 2; ++mt) {
                        mma16816(acc[mt][2 * np],     ah[mt], tl);
                        mma16816(acc[mt][2 * np + 1], ah[mt], tl + 2);
                        mma16816(acc[mt][2 * np],     al[mt], tb);
                        mma16816(acc[mt][2 * np + 1], al[mt], tb + 2);
                    }
                }
            }
        }
        __syncthreads();
    }

    // epilogue: direct register -> GMEM
#pragma unroll
    for (int mt = 0; mt < 2; ++mt) {
        int r0 = bm + wm + mt * 16 + (lane >> 2);
#pragma unroll
        for (int nt = 0; nt < 8; ++nt) {
            int c0 = bn + wn + nt * 8 + (lane & 3) * 2;
            float bx = bias ? __ldg(bias + c0) : 0.f;
            float by = bias ? __ldg(bias + c0 + 1) : 0.f;
            if (r0 < M) {
                float2 v = make_float2(acc[mt][nt][0] + bx, acc[mt][nt][1] + by);
                *(float2*)(C + (size_t)r0 * N + c0) = v;
            }
            if (r0 + 8 < M) {
                float2 v = make_float2(acc[mt][nt][2] + bx, acc[mt][nt][3] + by);
                *(float2*)(C + (size_t)(r0 + 8) * N + c0) = v;
            }
        }
    }
}

// ---------------- CSR construction ----------------
__global__ void k_zero_csr() {
    int i = blockIdx.x * blockDim.x + threadIdx.x;
    if (i < ME) g_degE[i] = 0;
    if (i < NV) g_degV[i] = 0;
}

__global__ void k_count(const int* __restrict__ vi, const int* __restrict__ ei) {
    int i = blockIdx.x * blockDim.x + threadIdx.x;
    if (i < EI) {
        atomicAdd(&g_degV[vi[i]], 1);
        atomicAdd(&g_degE[ei[i]], 1);
    }
}

__global__ void __launch_bounds__(1024)
k_scan(const int* __restrict__ cnt, int* __restrict__ off,
       int* __restrict__ cur, int n) {
    __shared__ int wsum[32];
    int tid = threadIdx.x, lane = tid & 31, w = tid >> 5;
    int chunk = (n + 1023) / 1024;
    int beg = min(tid * chunk, n);
    int end = min(beg + chunk, n);
    int s = 0;
    for (int i = beg; i < end; ++i) s += cnt[i];
    int v = s;
#pragma unroll
    for (int o = 1; o < 32; o <<= 1) {
        int u = __shfl_up_sync(0xffffffffu, v, o);
        if (lane >= o) v += u;
    }
    if (lane == 31) wsum[w] = v;
    __syncthreads();
    if (w == 0) {
        int ws = wsum[lane];
#pragma unroll
        for (int o = 1; o < 32; o <<= 1) {
            int u = __shfl_up_sync(0xffffffffu, ws, o);
            if (lane >= o) ws += u;
        }
        wsum[lane] = ws;
    }
    __syncthreads();
    int excl = v - s + (w > 0 ? wsum[w - 1] : 0);
    int run = excl;
    for (int i = beg; i < end; ++i) { off[i] = run; cur[i] = run; run += cnt[i]; }
    if (tid == 1023) off[n] = wsum[31];
}

__global__ void k_fill(const int* __restrict__ vi, const int* __restrict__ ei) {
    int i = blockIdx.x * blockDim.x + threadIdx.x;
    if (i < EI) {
        int v = vi[i], e = ei[i];
        g_elist[atomicAdd(&g_ecur[e], 1)] = v;
        g_vlist[atomicAdd(&g_vcur[v], 1)] = e;
    }
}

// ---------------- v2e mean (+ edge logit / + bf16 hi emission) -------------
template <int D, bool WE>
__global__ void __launch_bounds__(D / 4)
k_v2e(const float* __restrict__ Hp, const float* __restrict__ we,
      float* __restrict__ Y, float* __restrict__ alpha,
      __nv_bfloat16* __restrict__ Yhi) {
    constexpr int T = D / 4;
    int e = blockIdx.x;
    int beg = g_eoff[e], end = g_eoff[e + 1];
    int t = threadIdx.x;
    float4 acc = make_float4(0.f, 0.f, 0.f, 0.f);
    for (int i = beg; i < end; ++i) {
        const float4* row = (const float4*)(Hp + (size_t)g_elist[i] * D);
        float4 v = row[t];
        acc.x += v.x; acc.y += v.y; acc.z += v.z; acc.w += v.w;
    }
    float inv = 1.f / fmaxf((float)(end - beg), 1.f);
    float4 y = make_float4(acc.x * inv, acc.y * inv, acc.z * inv, acc.w * inv);
    ((float4*)(Y + (size_t)e * D))[t] = y;
    if (Yhi) {
        __nv_bfloat162* ph = (__nv_bfloat162*)(Yhi + (size_t)e * D);
        ph[2 * t]     = __nv_bfloat162(__float2bfloat16(y.x), __float2bfloat16(y.y));
        ph[2 * t + 1] = __nv_bfloat162(__float2bfloat16(y.z), __float2bfloat16(y.w));
    }
    if (WE) {
        float4 w4 = ((const float4*)we)[t];
        float dot = y.x * w4.x + y.y * w4.y + y.z * w4.z + y.w * w4.w;
        __shared__ float red[T];
        red[t] = dot;
        __syncthreads();
        for (int s = T / 2; s > 0; s >>= 1) {
            if (t < s) red[t] += red[t + s];
            __syncthreads();
        }
        if (t == 0) alpha[e] = red[0];
    }
}

// ---------------- per-vertex softmax stats over incident edges -------------
__global__ void k_vstats() {
    int v = blockIdx.x * blockDim.x + threadIdx.x;
    if (v >= NV) return;
    int beg = g_voff[v], end = g_voff[v + 1];
    float m = -INFINITY;
    for (int t = beg; t < end; ++t) {
        float a = g_alpha[g_vlist[t]];
        a = a > 0.f ? a : 0.2f * a;
        m = fmaxf(m, a);
    }
    float s = 0.f;
    for (int t = beg; t < end; ++t) {
        float a = g_alpha[g_vlist[t]];
        a = a > 0.f ? a : 0.2f * a;
        s += expf(a - m);
    }
    g_vm[v] = m;
    g_vwinv[v] = 1.f / (s + 1e-12f);
}

// ---------------- e2v: softmax-weighted sum (+ bf16 hi/lo emission) --------
template <int D, bool ELU>
__global__ void __launch_bounds__(D / 4)
k_e2v(const float* __restrict__ Y, float* __restrict__ Xo,
      __nv_bfloat16* __restrict__ Xhi, __nv_bfloat16* __restrict__ Xlo) {
    int v = blockIdx.x;
    int beg = g_voff[v], end = g_voff[v + 1];
    int t = threadIdx.x;
    float4 acc = make_float4(0.f, 0.f, 0.f, 0.f);
    float m = g_vm[v], winv = g_vwinv[v];
    for (int i = beg; i < end; ++i) {
        int e = g_vlist[i];
        float a = g_alpha[e];
        a = a > 0.f ? a : 0.2f * a;
        float w = expf(a - m) * winv;
        float4 yv = ((const float4*)(Y + (size_t)e * D))[t];
        acc.x += w * yv.x; acc.y += w * yv.y; acc.z += w * yv.z; acc.w += w * yv.w;
    }
    if (ELU) {
        acc.x = acc.x > 0.f ? acc.x : expm1f(acc.x);
        acc.y = acc.y > 0.f ? acc.y : expm1f(acc.y);
        acc.z = acc.z > 0.f ? acc.z : expm1f(acc.z);
        acc.w = acc.w > 0.f ? acc.w : expm1f(acc.w);
    }
    ((float4*)(Xo + (size_t)v * D))[t] = acc;
    if (Xhi) {
        float x[4] = {acc.x, acc.y, acc.z, acc.w};
        __nv_bfloat16 h[4];
#pragma unroll
        for (int j = 0; j < 4; ++j) h[j] = __float2bfloat16(x[j]);
        __nv_bfloat162* ph = (__nv_bfloat162*)(Xhi + (size_t)v * D);
        ph[2 * t]     = __nv_bfloat162(h[0], h[1]);
        ph[2 * t + 1] = __nv_bfloat162(h[2], h[3]);
        if (Xlo) {
            __nv_bfloat16 l[4];
#pragma unroll
            for (int j = 0; j < 4; ++j)
                l[j] = __float2bfloat16(x[j] - __bfloat162float(h[j]));
            __nv_bfloat162* pl = (__nv_bfloat162*)(Xlo + (size_t)v * D);
            pl[2 * t]     = __nv_bfloat162(l[0], l[1]);
            pl[2 * t + 1] = __nv_bfloat162(l[2], l[3]);
        }
    }
}

// ---------------- gated attention pieces ----------------
__global__ void __launch_bounds__(256)
k_logits(const float* __restrict__ AB, const float* __restrict__ ba,
         const float* __restrict__ bb, const float* __restrict__ Wc,
         const float* __restrict__ bc, float* __restrict__ logit) {
    int r = blockIdx.x, j = threadIdx.x;
    float av = tanhf(AB[(size_t)r * 512 + j] + ba[j]);
    float bv = AB[(size_t)r * 512 + 256 + j] + bb[j];
    float sg = 1.f / (1.f + expf(-bv));
    float v = av * sg * Wc[j];
    __shared__ float red[256];
    red[j] = v;
    __syncthreads();
    for (int s = 128; s > 0; s >>= 1) {
        if (j < s) red[j] += red[j + s];
        __syncthreads();
    }
    if (j == 0) logit[r] = red[0] + bc[0];
}

__global__ void k_attn_init() {
    int i = blockIdx.x * blockDim.x + threadIdx.x;
    if (i < CDIM) g_gvec[i] = 0.f;
    if (i == 0) { g_menc = 0u; g_S = 0.f; }
}

__global__ void __launch_bounds__(256)
k_maxred(const float* __restrict__ l, int n) {
    float m = -INFINITY;
    for (int i = blockIdx.x * blockDim.x + threadIdx.x; i < n; i += gridDim.x * blockDim.x)
        m = fmaxf(m, l[i]);
    __shared__ float red[256];
    red[threadIdx.x] = m;
    __syncthreads();
    for (int s = 128; s > 0; s >>= 1) {
        if (threadIdx.x < s) red[threadIdx.x] = fmaxf(red[threadIdx.x], red[threadIdx.x + s]);
        __syncthreads();
    }
    if (threadIdx.x == 0) atomicMax(&g_menc, fenc(red[0]));
}

__global__ void __launch_bounds__(256)
k_sumexp(const float* __restrict__ l, int n) {
    float m = fdec(g_menc);
    float s = 0.f;
    for (int i = blockIdx.x * blockDim.x + threadIdx.x; i < n; i += gridDim.x * blockDim.x)
        s += expf(l[i] - m);
    __shared__ float red[256];
    red[threadIdx.x] = s;
    __syncthreads();
    for (int st = 128; st > 0; st >>= 1) {
        if (threadIdx.x < st) red[threadIdx.x] += red[threadIdx.x + st];
        __syncthreads();
    }
    if (threadIdx.x == 0) atomicAdd(&g_S, red[0]);
}

__global__ void __launch_bounds__(256)
k_wsum(const float* __restrict__ x, const float* __restrict__ l, int n) {
    int c = blockIdx.x * 256 + threadIdx.x;
    float m = fdec(g_menc);
    float invS = 1.f / g_S;
    float acc = 0.f;
    for (int r = blockIdx.y; r < n; r += gridDim.y)
        acc += expf(l[r] - m) * invS * x[(size_t)r * CDIM + c];
    atomicAdd(&g_gvec[c], acc);
}

__global__ void k_gemv(const float* __restrict__ v, const float* __restrict__ W,
                       const float* __restrict__ b, float* __restrict__ out,
                       int R, int K) {
    int row = blockIdx.x * (blockDim.x >> 5) + (threadIdx.x >> 5);
    if (row >= R) return;
    int lane = threadIdx.x & 31;
    const float* wr = W + (size_t)row * K;
    float s = 0.f;
    for (int k = lane; k < K; k += 32) s += v[k] * wr[k];
    for (int o = 16; o; o >>= 1) s += __shfl_down_sync(0xffffffffu, s, o);
    if (lane == 0) out[row] = s + b[row];
}

__global__ void __launch_bounds__(256)
k_ln(const float* __restrict__ x, const float* __restrict__ g,
     const float* __restrict__ b, float* __restrict__ out, int D) {
    __shared__ float red[256];
    __shared__ float mu_s, rstd_s;
    float s = 0.f;
    for (int i = threadIdx.x; i < D; i += 256) s += x[i];
    red[threadIdx.x] = s;
    __syncthreads();
    for (int st = 128; st > 0; st >>= 1) {
        if (threadIdx.x < st) red[threadIdx.x] += red[threadIdx.x + st];
        __syncthreads();
    }
    if (threadIdx.x == 0) mu_s = red[0] / (float)D;
    __syncthreads();
    float mu = mu_s;
    float vs = 0.f;
    for (int i = threadIdx.x; i < D; i += 256) {
        float d = x[i] - mu;
        vs += d * d;
    }
    red[threadIdx.x] = vs;
    __syncthreads();
    for (int st = 128; st > 0; st >>= 1) {
        if (threadIdx.x < st) red[threadIdx.x] += red[threadIdx.x + st];
        __syncthreads();
    }
    if (threadIdx.x == 0) rstd_s = rsqrtf(red[0] / (float)D + 1e-5f);
    __syncthreads();
    float rstd = rstd_s;
    for (int i = threadIdx.x; i < D; i += 256)
        out[i] = (x[i] - mu) * rstd * g[i] + b[i];
}

// ---------------- host orchestration ----------------
extern "C" void kernel_launch(void* const* d_in, const int* in_sizes, int n_in,
                              void* d_out, int out_size) {
    float *bufA, *bufB, *bufC, *bufD, *Y, *ybuf, *ABy, *alpha, *logits;
    float *Wab, *gvec, *gout, *gcat, *gcatn;
    int *degE, *degV, *eoff, *voff, *ecur, *vcur;
    __nv_bfloat16 *Acthi, *Actlo, *Wt0hi, *Wt0lo, *Wt1hi, *Wt1lo, *Wabhi, *Wablo;
    cudaGetSymbolAddress((void**)&bufA, g_bufA);
    cudaGetSymbolAddress((void**)&bufB, g_bufB);
    cudaGetSymbolAddress((void**)&bufC, g_bufC);
    cudaGetSymbolAddress((void**)&bufD, g_bufD);
    cudaGetSymbolAddress((void**)&Y, g_Y);
    cudaGetSymbolAddress((void**)&ybuf, g_ybuf);
    cudaGetSymbolAddress((void**)&ABy, g_ABy);
    cudaGetSymbolAddress((void**)&alpha, g_alpha);
    cudaGetSymbolAddress((void**)&logits, g_logits);
    cudaGetSymbolAddress((void**)&Wab, g_Wab);
    cudaGetSymbolAddress((void**)&gvec, g_gvec);
    cudaGetSymbolAddress((void**)&gout, g_gout);
    cudaGetSymbolAddress((void**)&gcat, g_gcat);
    cudaGetSymbolAddress((void**)&gcatn, g_gcatn);
    cudaGetSymbolAddress((void**)&degE, g_degE);
    cudaGetSymbolAddress((void**)&degV, g_degV);
    cudaGetSymbolAddress((void**)&eoff, g_eoff);
    cudaGetSymbolAddress((void**)&voff, g_voff);
    cudaGetSymbolAddress((void**)&ecur, g_ecur);
    cudaGetSymbolAddress((void**)&vcur, g_vcur);
    cudaGetSymbolAddress((void**)&Acthi, g_Acthi);
    cudaGetSymbolAddress((void**)&Actlo, g_Actlo);
    cudaGetSymbolAddress((void**)&Wt0hi, g_Wt0hi);
    cudaGetSymbolAddress((void**)&Wt0lo, g_Wt0lo);
    cudaGetSymbolAddress((void**)&Wt1hi, g_Wt1hi);
    cudaGetSymbolAddress((void**)&Wt1lo, g_Wt1lo);
    cudaGetSymbolAddress((void**)&Wabhi, g_Wabhi);
    cudaGetSymbolAddress((void**)&Wablo, g_Wablo);

    const int GSMEM3 = 81920, GSMEM1 = 40960;
    cudaFuncSetAttribute(k_mma_gemm<true>, cudaFuncAttributeMaxDynamicSharedMemorySize, GSMEM3);
    cudaFuncSetAttribute(k_mma_gemm<false>, cudaFuncAttributeMaxDynamicSharedMemorySize, GSMEM1);

    // input index map (signature vs dict order)
    int xi[3], vii[3], eii[3];
    if (in_sizes[1] == NV * CDIM) {
        for (int b = 0; b < 3; ++b) { xi[b] = b; vii[b] = 3 + 2 * b; eii[b] = 4 + 2 * b; }
    } else {
        for (int b = 0; b < 3; ++b) { xi[b] = 3 * b; vii[b] = 3 * b + 1; eii[b] = 3 * b + 2; }
    }
    const float* Wt0  = (const float*)d_in[9];
    const float* bt0  = (const float*)d_in[10];
    const float* we0  = (const float*)d_in[11];
    const float* Wt1  = (const float*)d_in[12];
    const float* bt1  = (const float*)d_in[13];
    const float* we1  = (const float*)d_in[14];
    const float* Wa   = (const float*)d_in[15];
    const float* ba   = (const float*)d_in[16];
    const float* Wb   = (const float*)d_in[17];
    const float* bb   = (const float*)d_in[18];
    const float* Wc   = (const float*)d_in[19];
    const float* bc   = (const float*)d_in[20];
    const float* Wout = (const float*)d_in[21];
    const float* bout = (const float*)d_in[22];
    const float* gbn  = (const float*)d_in[23];
    const float* bbn  = (const float*)d_in[24];
    const float* gbn2 = (const float*)d_in[25];
    const float* bbn2 = (const float*)d_in[26];
    const float* Wf   = (const float*)d_in[27];
    const float* bf   = (const float*)d_in[28];

    const __nv_bfloat16* nbf = nullptr;
    const int EB = (EI + 255) / 256;

    // launches 1-2: assemble [Wa;Wb]
    cudaMemcpyAsync(Wab, Wa, (size_t)256 * 1024 * sizeof(float), cudaMemcpyDeviceToDevice, 0);
    cudaMemcpyAsync(Wab + 256 * 1024, Wb, (size_t)256 * 1024 * sizeof(float), cudaMemcpyDeviceToDevice, 0);
    // launches 3-5: splits needed for GEMM1 (+Wab for later) — GEMM1 lands at launch 6
    k_split<<<(NV * CDIM / 4 + 255) / 256, 256>>>((const float*)d_in[xi[0]], Acthi, Actlo, NV * CDIM / 4);
    k_split<<<512, 256>>>(Wt0, Wt0hi, Wt0lo, 512 * 1024 / 4);
    k_split<<<512, 256>>>(Wab, Wabhi, Wablo, 512 * 1024 / 4);

    for (int b = 0; b < 3; ++b) {
        const float* X = (const float*)d_in[xi[b]];
        const int* vi = (const int*)d_in[vii[b]];
        const int* ei = (const int*)d_in[eii[b]];

        if (b > 0)
            k_split<<<(NV * CDIM / 4 + 255) / 256, 256>>>(X, Acthi, Actlo, NV * CDIM / 4);

        // ----- layer 1 GEMM (C -> HID) — launch #6 on b==0, profiled by ncu -----
        {
            dim3 g(HIDD / 128, (NV + 127) / 128);
            k_mma_gemm<true><<<g, 256, GSMEM3>>>(Acthi, Actlo, Wt0hi, Wt0lo, bt0, bufA, NV, HIDD, CDIM);
        }
        if (b == 0)
            k_split<<<512, 256>>>(Wt1, Wt1hi, Wt1lo, 1024 * 512 / 4);

        // ----- CSR -----
        k_zero_csr<<<(NV + 255) / 256, 256>>>();
        k_count<<<EB, 256>>>(vi, ei);
        k_scan<<<1, 1024>>>(degE, eoff, ecur, ME);
        k_scan<<<1, 1024>>>(degV, voff, vcur, NV);
        k_fill<<<EB, 256>>>(vi, ei);

        // ----- layer 1 aggregation (elu), emit bf16 hi/lo for layer-2 GEMM -----
        k_v2e<HIDD, true><<<ME, HIDD / 4>>>(bufA, we0, Y, alpha, nullptr);
        k_vstats<<<(NV + 255) / 256, 256>>>();
        k_e2v<HIDD, true><<<NV, HIDD / 4>>>(Y, bufB, Acthi, Actlo);

        // ----- layer 2 (HID -> C, no elu) -----
        {
            dim3 g(CDIM / 128, (NV + 127) / 128);
            k_mma_gemm<true><<<g, 256, GSMEM3>>>(Acthi, Actlo, Wt1hi, Wt1lo, bt1, bufC, NV, CDIM, HIDD);
        }
        k_v2e<CDIM, true><<<ME, CDIM / 4>>>(bufC, we1, Y, alpha, nullptr);
        k_vstats<<<(NV + 255) / 256, 256>>>();
        // h: fp32 + bf16 hi (single-pass attention GEMM needs hi only)
        k_e2v<CDIM, false><<<NV, CDIM / 4>>>(Y, bufD, Acthi, nullptr);

        // ----- y = v2e_mean(h): fp32 + bf16 hi (into Actlo region) -----
        k_v2e<CDIM, false><<<ME, CDIM / 4>>>(bufD, nullptr, ybuf, alpha, Actlo);

        // ----- gated attention on h (20000 rows), single-pass bf16 -----
        {
            dim3 g(512 / 128, (NV + 127) / 128);
            k_mma_gemm<false><<<g, 256, GSMEM1>>>(Acthi, nbf, Wabhi, nbf,
                                                  (const float*)nullptr, bufA, NV, 512, CDIM);
        }
        k_logits<<<NV, 256>>>(bufA, ba, bb, Wc, bc, logits);
        k_attn_init<<<4, 256>>>();
        k_maxred<<<40, 256>>>(logits, NV);
        k_sumexp<<<40, 256>>>(logits, NV);
        {
            dim3 g(CDIM / 256, 125);
            k_wsum<<<g, 256>>>(bufD, logits, NV);
        }
        k_gemv<<<128, 256>>>(gvec, Wout, bout, gout, CDIM, CDIM);
        k_ln<<<1, 256>>>(gout, gbn, bbn, gcat + (size_t)b * CDIM, CDIM);

        // ----- gated attention on y (5000 rows), single-pass bf16 -----
        {
            dim3 g(512 / 128, (ME + 127) / 128);
            k_mma_gemm<false><<<g, 256, GSMEM1>>>(Actlo, nbf, Wabhi, nbf,
                                                  (const float*)nullptr, ABy, ME, 512, CDIM);
        }
        k_logits<<<ME, 256>>>(ABy, ba, bb, Wc, bc, logits);
        k_attn_init<<<4, 256>>>();
        k_maxred<<<20, 256>>>(logits, ME);
        k_sumexp<<<20, 256>>>(logits, ME);
        {
            dim3 g(CDIM / 256, 125);
            k_wsum<<<g, 256>>>(ybuf, logits, ME);
        }
        k_gemv<<<128, 256>>>(gvec, Wout, bout, gout, CDIM, CDIM);
        k_ln<<<1, 256>>>(gout, gbn, bbn, gcat + (size_t)(3 + b) * CDIM, CDIM);
    }

    // ----- final: LN(concat) @ Wf^T + bf -----
    k_ln<<<1, 256>>>(gcat, gbn2, bbn2, gcatn, 6 * CDIM);
    k_gemv<<<2, 256>>>(gcatn, Wf, bf, (float*)d_out, 10, 6 * CDIM);
}

// round 6
// speedup vs baseline: 3.4608x; 1.2386x over previous
#include <cuda_runtime.h>
#include <cuda_bf16.h>
#include <math.h>
#include <stdint.h>

// Problem constants
#define NV   20000
#define ME   5000
#define EI   160000
#define CDIM 1024
#define HIDD 512
#define NB   3

// ---------------- device scratch (static, no allocation) ----------------
// per-branch buffers for 3-stream concurrency
__device__ __align__(16) float g_bufA[NB][(size_t)NV * HIDD];
__device__ __align__(16) float g_bufC[NB][(size_t)NV * CDIM];
__device__ __align__(16) float g_bufD[NB][(size_t)NV * CDIM];
__device__ __align__(16) float g_Y[NB][(size_t)ME * CDIM];
__device__ __align__(16) float g_ybuf[NB][(size_t)ME * CDIM];
__device__ __align__(16) float g_ABy[NB][(size_t)ME * HIDD];
__device__ float g_alpha[NB][ME];
__device__ float g_vm[NB][NV];
__device__ float g_vwinv[NB][NV];
__device__ float g_logits[NB][NV];

__device__ int g_degE[NB][ME], g_eoff[NB][ME + 1], g_ecur[NB][ME];
__device__ int g_degV[NB][NV], g_voff[NB][NV + 1], g_vcur[NB][NV];
__device__ int g_elist[NB][EI];
__device__ int g_vlist[NB][EI];

__device__ float g_gvec[NB][CDIM];
__device__ float g_gout[NB][CDIM];
__device__ unsigned g_menc[NB];
__device__ float g_S[NB];

__device__ __align__(16) __nv_bfloat16 g_Acthi[NB][(size_t)NV * CDIM];
__device__ __align__(16) __nv_bfloat16 g_Actlo[NB][(size_t)NV * CDIM];

// shared
__device__ __align__(16) float g_Wab[512 * 1024];
__device__ float g_gcat[6 * CDIM];
__device__ float g_gcatn[6 * CDIM];
__device__ __align__(16) __nv_bfloat16 g_Wt0hi[512 * 1024], g_Wt0lo[512 * 1024];
__device__ __align__(16) __nv_bfloat16 g_Wt1hi[1024 * 512], g_Wt1lo[1024 * 512];
__device__ __align__(16) __nv_bfloat16 g_Wabhi[512 * 1024], g_Wablo[512 * 1024];

// ---------------- helpers ----------------
__device__ __forceinline__ uint32_t smem_u32(const void* p) {
    uint32_t a;
    asm("{ .reg .u64 t; cvta.to.shared.u64 t, %1; cvt.u32.u64 %0, t; }"
        : "=r"(a) : "l"(p));
    return a;
}

__device__ __forceinline__ void cp_cg(uint32_t s, const void* g, int bytes) {
    asm volatile("cp.async.cg.shared.global [%0], [%1], 16, %2;"
                 :: "r"(s), "l"(g), "r"(bytes) : "memory");
}

__device__ __forceinline__ void ldsm4(uint32_t* r, uint32_t addr) {
    asm volatile("ldmatrix.sync.aligned.m8n8.x4.shared.b16 {%0,%1,%2,%3}, [%4];"
                 : "=r"(r[0]), "=r"(r[1]), "=r"(r[2]), "=r"(r[3]) : "r"(addr));
}

__device__ __forceinline__ void mma16816(float* d, const uint32_t* a, const uint32_t* b) {
    asm volatile(
        "mma.sync.aligned.m16n8k16.row.col.f32.bf16.bf16.f32 "
        "{%0,%1,%2,%3}, {%4,%5,%6,%7}, {%8,%9}, {%0,%1,%2,%3};"
        : "+f"(d[0]), "+f"(d[1]), "+f"(d[2]), "+f"(d[3])
        : "r"(a[0]), "r"(a[1]), "r"(a[2]), "r"(a[3]), "r"(b[0]), "r"(b[1]));
}

__device__ __forceinline__ unsigned fenc(float f) {
    unsigned u = __float_as_uint(f);
    return (u & 0x80000000u) ? ~u : (u | 0x80000000u);
}
__device__ __forceinline__ float fdec(unsigned e) {
    unsigned u = (e & 0x80000000u) ? (e & 0x7FFFFFFFu) : ~e;
    return __uint_as_float(u);
}

// ---------------- fp32 -> bf16 hi/lo split ----------------
__global__ void __launch_bounds__(256)
k_split(const float* __restrict__ src, __nv_bfloat16* __restrict__ hi,
        __nv_bfloat16* __restrict__ lo, int n4) {
    int i = blockIdx.x * blockDim.x + threadIdx.x;
    if (i >= n4) return;
    float4 v = ((const float4*)src)[i];
    __nv_bfloat16 h[4], l[4];
    float x[4] = {v.x, v.y, v.z, v.w};
#pragma unroll
    for (int j = 0; j < 4; ++j) {
        h[j] = __float2bfloat16(x[j]);
        l[j] = __float2bfloat16(x[j] - __bfloat162float(h[j]));
    }
    ((__nv_bfloat162*)hi)[2 * i]     = __nv_bfloat162(h[0], h[1]);
    ((__nv_bfloat162*)hi)[2 * i + 1] = __nv_bfloat162(h[2], h[3]);
    ((__nv_bfloat162*)lo)[2 * i]     = __nv_bfloat162(l[0], l[1]);
    ((__nv_bfloat162*)lo)[2 * i + 1] = __nv_bfloat162(l[2], l[3]);
}

// ---------------- bf16 tensor-core GEMM: C = A @ B^T + bias ----------------
// Identical compute structure to R5 (128 regs, 2 CTAs/SM).
template <bool S3>
__global__ void __launch_bounds__(256, 2)
k_mma_gemm(const __nv_bfloat16* __restrict__ Ahi, const __nv_bfloat16* __restrict__ Alo,
           const __nv_bfloat16* __restrict__ Bhi, const __nv_bfloat16* __restrict__ Blo,
           const float* __restrict__ bias, float* __restrict__ C,
           int M, int N, int K) {
    extern __shared__ char smraw[];
    uint32_t sb = smem_u32(smraw);
    constexpr int OFF_AL = 10240;
    constexpr int OFF_BH = S3 ? 20480 : 10240;
    constexpr int OFF_BL = 30720;
    constexpr int STG = S3 ? 40960 : 20480;
    int tid = threadIdx.x, lane = tid & 31, warp = tid >> 5;
    int wm = (warp & 3) * 32;
    int wn = (warp >> 2) * 64;
    int bm = blockIdx.y * 128, bn = blockIdx.x * 128;

    float acc[2][8][4];
#pragma unroll
    for (int a = 0; a < 2; ++a)
#pragma unroll
        for (int b = 0; b < 8; ++b)
#pragma unroll
            for (int c = 0; c < 4; ++c) acc[a][b][c] = 0.f;

    auto issue = [&](int kt, int s) {
        int k0 = kt * 32;
        uint32_t sbase = sb + s * STG;
#pragma unroll
        for (int i = 0; i < 2; ++i) {
            int idx = i * 256 + tid;
            int row = idx >> 2, c = idx & 3;
            uint32_t soff = sbase + row * 80 + c * 16;
            int ar = bm + row;
            int pa = (ar < M) ? 16 : 0;
            int arc = (ar < M) ? ar : 0;
            cp_cg(soff,          Ahi + (size_t)arc * K + k0 + c * 8, pa);
            cp_cg(soff + OFF_BH, Bhi + (size_t)(bn + row) * K + k0 + c * 8, 16);
            if (S3) {
                cp_cg(soff + OFF_AL, Alo + (size_t)arc * K + k0 + c * 8, pa);
                cp_cg(soff + OFF_BL, Blo + (size_t)(bn + row) * K + k0 + c * 8, 16);
            }
        }
        asm volatile("cp.async.commit_group;" ::: "memory");
    };

    int KT = K / 32;
    issue(0, 0);
    for (int kt = 0; kt < KT; ++kt) {
        int s = kt & 1;
        if (kt + 1 < KT) {
            issue(kt + 1, s ^ 1);
            asm volatile("cp.async.wait_group 1;" ::: "memory");
        } else {
            asm volatile("cp.async.wait_group 0;" ::: "memory");
        }
        __syncthreads();
        uint32_t sbase = sb + s * STG;
#pragma unroll
        for (int kk = 0; kk < 2; ++kk) {
            uint32_t ah[2][4], al[2][4];
#pragma unroll
            for (int mt = 0; mt < 2; ++mt) {
                uint32_t addr = sbase + (uint32_t)(wm + mt * 16 + (lane & 15)) * 80
                              + kk * 32 + (lane >> 4) * 16;
                ldsm4(ah[mt], addr);
                if (S3) ldsm4(al[mt], addr + OFF_AL);
            }
#pragma unroll
            for (int np = 0; np < 4; ++np) {
                int row = wn + np * 16 + (lane & 7) + ((lane >> 4) << 3);
                uint32_t addr = sbase + OFF_BH + (uint32_t)row * 80
                              + kk * 32 + ((lane >> 3) & 1) * 16;
                uint32_t tb[4];
                ldsm4(tb, addr);
#pragma unroll
                for (int mt = 0; mt < 2; ++mt) {
                    mma16816(acc[mt][2 * np],     ah[mt], tb);
                    mma16816(acc[mt][2 * np + 1], ah[mt], tb + 2);
                }
                if (S3) {
                    uint32_t tl[4];
                    ldsm4(tl, addr + (OFF_BL - OFF_BH));
#pragma unroll
                    for (int mt = 0; mt < 2; ++mt) {
                        mma16816(acc[mt][2 * np],     ah[mt], tl);
                        mma16816(acc[mt][2 * np + 1], ah[mt], tl + 2);
                        mma16816(acc[mt][2 * np],     al[mt], tb);
                        mma16816(acc[mt][2 * np + 1], al[mt], tb + 2);
                    }
                }
            }
        }
        __syncthreads();
    }

#pragma unroll
    for (int mt = 0; mt < 2; ++mt) {
        int r0 = bm + wm + mt * 16 + (lane >> 2);
#pragma unroll
        for (int nt = 0; nt < 8; ++nt) {
            int c0 = bn + wn + nt * 8 + (lane & 3) * 2;
            float bx = bias ? __ldg(bias + c0) : 0.f;
            float by = bias ? __ldg(bias + c0 + 1) : 0.f;
            if (r0 < M) {
                float2 v = make_float2(acc[mt][nt][0] + bx, acc[mt][nt][1] + by);
                *(float2*)(C + (size_t)r0 * N + c0) = v;
            }
            if (r0 + 8 < M) {
                float2 v = make_float2(acc[mt][nt][2] + bx, acc[mt][nt][3] + by);
                *(float2*)(C + (size_t)(r0 + 8) * N + c0) = v;
            }
        }
    }
}

// ---------------- CSR construction (pointer-parameterized) ----------------
__global__ void k_zero_csr(int* __restrict__ degE, int* __restrict__ degV) {
    int i = blockIdx.x * blockDim.x + threadIdx.x;
    if (i < ME) degE[i] = 0;
    if (i < NV) degV[i] = 0;
}

__global__ void k_count(const int* __restrict__ vi, const int* __restrict__ ei,
                        int* __restrict__ degV, int* __restrict__ degE) {
    int i = blockIdx.x * blockDim.x + threadIdx.x;
    if (i < EI) {
        atomicAdd(&degV[vi[i]], 1);
        atomicAdd(&degE[ei[i]], 1);
    }
}

__global__ void __launch_bounds__(1024)
k_scan(const int* __restrict__ cnt, int* __restrict__ off,
       int* __restrict__ cur, int n) {
    __shared__ int wsum[32];
    int tid = threadIdx.x, lane = tid & 31, w = tid >> 5;
    int chunk = (n + 1023) / 1024;
    int beg = min(tid * chunk, n);
    int end = min(beg + chunk, n);
    int s = 0;
    for (int i = beg; i < end; ++i) s += cnt[i];
    int v = s;
#pragma unroll
    for (int o = 1; o < 32; o <<= 1) {
        int u = __shfl_up_sync(0xffffffffu, v, o);
        if (lane >= o) v += u;
    }
    if (lane == 31) wsum[w] = v;
    __syncthreads();
    if (w == 0) {
        int ws = wsum[lane];
#pragma unroll
        for (int o = 1; o < 32; o <<= 1) {
            int u = __shfl_up_sync(0xffffffffu, ws, o);
            if (lane >= o) ws += u;
        }
        wsum[lane] = ws;
    }
    __syncthreads();
    int excl = v - s + (w > 0 ? wsum[w - 1] : 0);
    int run = excl;
    for (int i = beg; i < end; ++i) { off[i] = run; cur[i] = run; run += cnt[i]; }
    if (tid == 1023) off[n] = wsum[31];
}

__global__ void k_fill(const int* __restrict__ vi, const int* __restrict__ ei,
                       int* __restrict__ ecur, int* __restrict__ vcur,
                       int* __restrict__ elist, int* __restrict__ vlist) {
    int i = blockIdx.x * blockDim.x + threadIdx.x;
    if (i < EI) {
        int v = vi[i], e = ei[i];
        elist[atomicAdd(&ecur[e], 1)] = v;
        vlist[atomicAdd(&vcur[v], 1)] = e;
    }
}

// ---------------- v2e mean (+ edge logit / + bf16 hi emission) -------------
template <int D, bool WE>
__global__ void __launch_bounds__(D / 4)
k_v2e(const float* __restrict__ Hp, const float* __restrict__ we,
      float* __restrict__ Y, float* __restrict__ alpha,
      __nv_bfloat16* __restrict__ Yhi,
      const int* __restrict__ eoff, const int* __restrict__ elist) {
    constexpr int T = D / 4;
    int e = blockIdx.x;
    int beg = eoff[e], end = eoff[e + 1];
    int t = threadIdx.x;
    float4 acc = make_float4(0.f, 0.f, 0.f, 0.f);
    for (int i = beg; i < end; ++i) {
        const float4* row = (const float4*)(Hp + (size_t)elist[i] * D);
        float4 v = row[t];
        acc.x += v.x; acc.y += v.y; acc.z += v.z; acc.w += v.w;
    }
    float inv = 1.f / fmaxf((float)(end - beg), 1.f);
    float4 y = make_float4(acc.x * inv, acc.y * inv, acc.z * inv, acc.w * inv);
    ((float4*)(Y + (size_t)e * D))[t] = y;
    if (Yhi) {
        __nv_bfloat162* ph = (__nv_bfloat162*)(Yhi + (size_t)e * D);
        ph[2 * t]     = __nv_bfloat162(__float2bfloat16(y.x), __float2bfloat16(y.y));
        ph[2 * t + 1] = __nv_bfloat162(__float2bfloat16(y.z), __float2bfloat16(y.w));
    }
    if (WE) {
        float4 w4 = ((const float4*)we)[t];
        float dot = y.x * w4.x + y.y * w4.y + y.z * w4.z + y.w * w4.w;
        __shared__ float red[T];
        red[t] = dot;
        __syncthreads();
        for (int s = T / 2; s > 0; s >>= 1) {
            if (t < s) red[t] += red[t + s];
            __syncthreads();
        }
        if (t == 0) alpha[e] = red[0];
    }
}

// ---------------- per-vertex softmax stats over incident edges -------------
__global__ void k_vstats(const float* __restrict__ alpha,
                         const int* __restrict__ voff, const int* __restrict__ vlist,
                         float* __restrict__ vm, float* __restrict__ vwinv) {
    int v = blockIdx.x * blockDim.x + threadIdx.x;
    if (v >= NV) return;
    int beg = voff[v], end = voff[v + 1];
    float m = -INFINITY;
    for (int t = beg; t < end; ++t) {
        float a = alpha[vlist[t]];
        a = a > 0.f ? a : 0.2f * a;
        m = fmaxf(m, a);
    }
    float s = 0.f;
    for (int t = beg; t < end; ++t) {
        float a = alpha[vlist[t]];
        a = a > 0.f ? a : 0.2f * a;
        s += expf(a - m);
    }
    vm[v] = m;
    vwinv[v] = 1.f / (s + 1e-12f);
}

// ---------------- e2v: softmax-weighted sum (+ bf16 hi/lo emission) --------
template <int D, bool ELU>
__global__ void __launch_bounds__(D / 4)
k_e2v(const float* __restrict__ Y, float* __restrict__ Xo,
      __nv_bfloat16* __restrict__ Xhi, __nv_bfloat16* __restrict__ Xlo,
      const int* __restrict__ voff, const int* __restrict__ vlist,
      const float* __restrict__ alpha,
      const float* __restrict__ vm, const float* __restrict__ vwinv) {
    int v = blockIdx.x;
    int beg = voff[v], end = voff[v + 1];
    int t = threadIdx.x;
    float4 acc = make_float4(0.f, 0.f, 0.f, 0.f);
    float m = vm[v], winv = vwinv[v];
    for (int i = beg; i < end; ++i) {
        int e = vlist[i];
        float a = alpha[e];
        a = a > 0.f ? a : 0.2f * a;
        float w = expf(a - m) * winv;
        float4 yv = ((const float4*)(Y + (size_t)e * D))[t];
        acc.x += w * yv.x; acc.y += w * yv.y; acc.z += w * yv.z; acc.w += w * yv.w;
    }
    if (ELU) {
        acc.x = acc.x > 0.f ? acc.x : expm1f(acc.x);
        acc.y = acc.y > 0.f ? acc.y : expm1f(acc.y);
        acc.z = acc.z > 0.f ? acc.z : expm1f(acc.z);
        acc.w = acc.w > 0.f ? acc.w : expm1f(acc.w);
    }
    if (Xo) ((float4*)(Xo + (size_t)v * D))[t] = acc;
    if (Xhi) {
        float x[4] = {acc.x, acc.y, acc.z, acc.w};
        __nv_bfloat16 h[4];
#pragma unroll
        for (int j = 0; j < 4; ++j) h[j] = __float2bfloat16(x[j]);
        __nv_bfloat162* ph = (__nv_bfloat162*)(Xhi + (size_t)v * D);
        ph[2 * t]     = __nv_bfloat162(h[0], h[1]);
        ph[2 * t + 1] = __nv_bfloat162(h[2], h[3]);
        if (Xlo) {
            __nv_bfloat16 l[4];
#pragma unroll
            for (int j = 0; j < 4; ++j)
                l[j] = __float2bfloat16(x[j] - __bfloat162float(h[j]));
            __nv_bfloat162* pl = (__nv_bfloat162*)(Xlo + (size_t)v * D);
            pl[2 * t]     = __nv_bfloat162(l[0], l[1]);
            pl[2 * t + 1] = __nv_bfloat162(l[2], l[3]);
        }
    }
}

// ---------------- gated attention pieces ----------------
__global__ void __launch_bounds__(256)
k_logits(const float* __restrict__ AB, const float* __restrict__ ba,
         const float* __restrict__ bb, const float* __restrict__ Wc,
         const float* __restrict__ bc, float* __restrict__ logit) {
    int r = blockIdx.x, j = threadIdx.x;
    float av = tanhf(AB[(size_t)r * 512 + j] + ba[j]);
    float bv = AB[(size_t)r * 512 + 256 + j] + bb[j];
    float sg = 1.f / (1.f + expf(-bv));
    float v = av * sg * Wc[j];
    __shared__ float red[256];
    red[j] = v;
    __syncthreads();
    for (int s = 128; s > 0; s >>= 1) {
        if (j < s) red[j] += red[j + s];
        __syncthreads();
    }
    if (j == 0) logit[r] = red[0] + bc[0];
}

__global__ void k_attn_init(float* __restrict__ gvec, unsigned* __restrict__ menc,
                            float* __restrict__ S) {
    int i = blockIdx.x * blockDim.x + threadIdx.x;
    if (i < CDIM) gvec[i] = 0.f;
    if (i == 0) { *menc = 0u; *S = 0.f; }
}

__global__ void __launch_bounds__(256)
k_maxred(const float* __restrict__ l, int n, unsigned* __restrict__ menc) {
    float m = -INFINITY;
    for (int i = blockIdx.x * blockDim.x + threadIdx.x; i < n; i += gridDim.x * blockDim.x)
        m = fmaxf(m, l[i]);
    __shared__ float red[256];
    red[threadIdx.x] = m;
    __syncthreads();
    for (int s = 128; s > 0; s >>= 1) {
        if (threadIdx.x < s) red[threadIdx.x] = fmaxf(red[threadIdx.x], red[threadIdx.x + s]);
        __syncthreads();
    }
    if (threadIdx.x == 0) atomicMax(menc, fenc(red[0]));
}

__global__ void __launch_bounds__(256)
k_sumexp(const float* __restrict__ l, int n, const unsigned* __restrict__ menc,
         float* __restrict__ S) {
    float m = fdec(*menc);
    float s = 0.f;
    for (int i = blockIdx.x * blockDim.x + threadIdx.x; i < n; i += gridDim.x * blockDim.x)
        s += expf(l[i] - m);
    __shared__ float red[256];
    red[threadIdx.x] = s;
    __syncthreads();
    for (int st = 128; st > 0; st >>= 1) {
        if (threadIdx.x < st) red[threadIdx.x] += red[threadIdx.x + st];
        __syncthreads();
    }
    if (threadIdx.x == 0) atomicAdd(S, red[0]);
}

__global__ void __launch_bounds__(256)
k_wsum(const float* __restrict__ x, const float* __restrict__ l, int n,
       const unsigned* __restrict__ menc, const float* __restrict__ S,
       float* __restrict__ gvec) {
    int c = blockIdx.x * 256 + threadIdx.x;
    float m = fdec(*menc);
    float invS = 1.f / *S;
    float acc = 0.f;
    for (int r = blockIdx.y; r < n; r += gridDim.y)
        acc += expf(l[r] - m) * invS * x[(size_t)r * CDIM + c];
    atomicAdd(&gvec[c], acc);
}

__global__ void k_gemv(const float* __restrict__ v, const float* __restrict__ W,
                       const float* __restrict__ b, float* __restrict__ out,
                       int R, int K) {
    int row = blockIdx.x * (blockDim.x >> 5) + (threadIdx.x >> 5);
    if (row >= R) return;
    int lane = threadIdx.x & 31;
    const float* wr = W + (size_t)row * K;
    float s = 0.f;
    for (int k = lane; k < K; k += 32) s += v[k] * wr[k];
    for (int o = 16; o; o >>= 1) s += __shfl_down_sync(0xffffffffu, s, o);
    if (lane == 0) out[row] = s + b[row];
}

__global__ void __launch_bounds__(256)
k_ln(const float* __restrict__ x, const float* __restrict__ g,
     const float* __restrict__ b, float* __restrict__ out, int D) {
    __shared__ float red[256];
    __shared__ float mu_s, rstd_s;
    float s = 0.f;
    for (int i = threadIdx.x; i < D; i += 256) s += x[i];
    red[threadIdx.x] = s;
    __syncthreads();
    for (int st = 128; st > 0; st >>= 1) {
        if (threadIdx.x < st) red[threadIdx.x] += red[threadIdx.x + st];
        __syncthreads();
    }
    if (threadIdx.x == 0) mu_s = red[0] / (float)D;
    __syncthreads();
    float mu = mu_s;
    float vs = 0.f;
    for (int i = threadIdx.x; i < D; i += 256) {
        float d = x[i] - mu;
        vs += d * d;
    }
    red[threadIdx.x] = vs;
    __syncthreads();
    for (int st = 128; st > 0; st >>= 1) {
        if (threadIdx.x < st) red[threadIdx.x] += red[threadIdx.x + st];
        __syncthreads();
    }
    if (threadIdx.x == 0) rstd_s = rsqrtf(red[0] / (float)D + 1e-5f);
    __syncthreads();
    float rstd = rstd_s;
    for (int i = threadIdx.x; i < D; i += 256)
        out[i] = (x[i] - mu) * rstd * g[i] + b[i];
}

// ---------------- host orchestration ----------------
extern "C" void kernel_launch(void* const* d_in, const int* in_sizes, int n_in,
                              void* d_out, int out_size) {
    // lazy one-time stream/event infra (host objects only; identical behavior
    // on every call — all work is re-issued each call)
    static cudaStream_t st[NB];
    static cudaEvent_t evR, evD[NB];
    static bool inited = false;
    if (!inited) {
        for (int i = 0; i < NB; ++i)
            cudaStreamCreateWithFlags(&st[i], cudaStreamNonBlocking);
        cudaEventCreateWithFlags(&evR, cudaEventDisableTiming);
        for (int i = 0; i < NB; ++i)
            cudaEventCreateWithFlags(&evD[i], cudaEventDisableTiming);
        inited = true;
    }

    // resolve symbol base addresses
    float *bufA0, *bufC0, *bufD0, *Y0, *ybuf0, *ABy0, *alpha0, *vm0, *vwinv0, *logits0;
    float *Wab, *gvec0, *gout0, *gcat, *gcatn, *S0;
    unsigned* menc0;
    int *degE0, *eoff0, *ecur0, *degV0, *voff0, *vcur0, *elist0, *vlist0;
    __nv_bfloat16 *Acthi0, *Actlo0, *Wt0hi, *Wt0lo, *Wt1hi, *Wt1lo, *Wabhi, *Wablo;
    cudaGetSymbolAddress((void**)&bufA0, g_bufA);
    cudaGetSymbolAddress((void**)&bufC0, g_bufC);
    cudaGetSymbolAddress((void**)&bufD0, g_bufD);
    cudaGetSymbolAddress((void**)&Y0, g_Y);
    cudaGetSymbolAddress((void**)&ybuf0, g_ybuf);
    cudaGetSymbolAddress((void**)&ABy0, g_ABy);
    cudaGetSymbolAddress((void**)&alpha0, g_alpha);
    cudaGetSymbolAddress((void**)&vm0, g_vm);
    cudaGetSymbolAddress((void**)&vwinv0, g_vwinv);
    cudaGetSymbolAddress((void**)&logits0, g_logits);
    cudaGetSymbolAddress((void**)&Wab, g_Wab);
    cudaGetSymbolAddress((void**)&gvec0, g_gvec);
    cudaGetSymbolAddress((void**)&gout0, g_gout);
    cudaGetSymbolAddress((void**)&gcat, g_gcat);
    cudaGetSymbolAddress((void**)&gcatn, g_gcatn);
    cudaGetSymbolAddress((void**)&menc0, g_menc);
    cudaGetSymbolAddress((void**)&S0, g_S);
    cudaGetSymbolAddress((void**)&degE0, g_degE);
    cudaGetSymbolAddress((void**)&eoff0, g_eoff);
    cudaGetSymbolAddress((void**)&ecur0, g_ecur);
    cudaGetSymbolAddress((void**)&degV0, g_degV);
    cudaGetSymbolAddress((void**)&voff0, g_voff);
    cudaGetSymbolAddress((void**)&vcur0, g_vcur);
    cudaGetSymbolAddress((void**)&elist0, g_elist);
    cudaGetSymbolAddress((void**)&vlist0, g_vlist);
    cudaGetSymbolAddress((void**)&Acthi0, g_Acthi);
    cudaGetSymbolAddress((void**)&Actlo0, g_Actlo);
    cudaGetSymbolAddress((void**)&Wt0hi, g_Wt0hi);
    cudaGetSymbolAddress((void**)&Wt0lo, g_Wt0lo);
    cudaGetSymbolAddress((void**)&Wt1hi, g_Wt1hi);
    cudaGetSymbolAddress((void**)&Wt1lo, g_Wt1lo);
    cudaGetSymbolAddress((void**)&Wabhi, g_Wabhi);
    cudaGetSymbolAddress((void**)&Wablo, g_Wablo);

    const int GSMEM3 = 81920, GSMEM1 = 40960;
    cudaFuncSetAttribute(k_mma_gemm<true>, cudaFuncAttributeMaxDynamicSharedMemorySize, GSMEM3);
    cudaFuncSetAttribute(k_mma_gemm<false>, cudaFuncAttributeMaxDynamicSharedMemorySize, GSMEM1);

    // input index map (signature vs dict order)
    int xi[3], vii[3], eii[3];
    if (in_sizes[1] == NV * CDIM) {
        for (int b = 0; b < 3; ++b) { xi[b] = b; vii[b] = 3 + 2 * b; eii[b] = 4 + 2 * b; }
    } else {
        for (int b = 0; b < 3; ++b) { xi[b] = 3 * b; vii[b] = 3 * b + 1; eii[b] = 3 * b + 2; }
    }
    const float* Wt0  = (const float*)d_in[9];
    const float* bt0  = (const float*)d_in[10];
    const float* we0  = (const float*)d_in[11];
    const float* Wt1  = (const float*)d_in[12];
    const float* bt1  = (const float*)d_in[13];
    const float* we1  = (const float*)d_in[14];
    const float* Wa   = (const float*)d_in[15];
    const float* ba   = (const float*)d_in[16];
    const float* Wb   = (const float*)d_in[17];
    const float* bb   = (const float*)d_in[18];
    const float* Wc   = (const float*)d_in[19];
    const float* bc   = (const float*)d_in[20];
    const float* Wout = (const float*)d_in[21];
    const float* bout = (const float*)d_in[22];
    const float* gbn  = (const float*)d_in[23];
    const float* bbn  = (const float*)d_in[24];
    const float* gbn2 = (const float*)d_in[25];
    const float* bbn2 = (const float*)d_in[26];
    const float* Wf   = (const float*)d_in[27];
    const float* bf   = (const float*)d_in[28];

    const __nv_bfloat16* nbf = nullptr;
    const int EB = (EI + 255) / 256;

    // shared weight prep on the capture (default) stream
    cudaMemcpyAsync(Wab, Wa, (size_t)256 * 1024 * sizeof(float), cudaMemcpyDeviceToDevice, 0);
    cudaMemcpyAsync(Wab + 256 * 1024, Wb, (size_t)256 * 1024 * sizeof(float), cudaMemcpyDeviceToDevice, 0);
    k_split<<<512, 256>>>(Wt0, Wt0hi, Wt0lo, 512 * 1024 / 4);
    k_split<<<512, 256>>>(Wt1, Wt1hi, Wt1lo, 1024 * 512 / 4);
    k_split<<<512, 256>>>(Wab, Wabhi, Wablo, 512 * 1024 / 4);

    // fork three branch streams
    cudaEventRecord(evR, 0);
    for (int b = 0; b < NB; ++b) cudaStreamWaitEvent(st[b], evR, 0);

    for (int b = 0; b < NB; ++b) {
        cudaStream_t s = st[b];
        const float* X = (const float*)d_in[xi[b]];
        const int* vi = (const int*)d_in[vii[b]];
        const int* ei = (const int*)d_in[eii[b]];

        float* bufA = bufA0 + (size_t)b * NV * HIDD;
        float* bufC = bufC0 + (size_t)b * NV * CDIM;
        float* bufD = bufD0 + (size_t)b * NV * CDIM;
        float* Y    = Y0    + (size_t)b * ME * CDIM;
        float* ybuf = ybuf0 + (size_t)b * ME * CDIM;
        float* ABy  = ABy0  + (size_t)b * ME * HIDD;
        float* alpha = alpha0 + (size_t)b * ME;
        float* vm = vm0 + (size_t)b * NV;
        float* vwinv = vwinv0 + (size_t)b * NV;
        float* logits = logits0 + (size_t)b * NV;
        float* gvec = gvec0 + (size_t)b * CDIM;
        float* gout = gout0 + (size_t)b * CDIM;
        unsigned* menc = menc0 + b;
        float* S = S0 + b;
        int* degE = degE0 + (size_t)b * ME;
        int* eoff = eoff0 + (size_t)b * (ME + 1);
        int* ecur = ecur0 + (size_t)b * ME;
        int* degV = degV0 + (size_t)b * NV;
        int* voff = voff0 + (size_t)b * (NV + 1);
        int* vcur = vcur0 + (size_t)b * NV;
        int* elist = elist0 + (size_t)b * EI;
        int* vlist = vlist0 + (size_t)b * EI;
        __nv_bfloat16* Acthi = Acthi0 + (size_t)b * NV * CDIM;
        __nv_bfloat16* Actlo = Actlo0 + (size_t)b * NV * CDIM;

        // activation split for layer-1 GEMM
        k_split<<<(NV * CDIM / 4 + 255) / 256, 256, 0, s>>>(X, Acthi, Actlo, NV * CDIM / 4);

        // layer 1 GEMM (C -> HID)
        {
            dim3 g(HIDD / 128, (NV + 127) / 128);
            k_mma_gemm<true><<<g, 256, GSMEM3, s>>>(Acthi, Actlo, Wt0hi, Wt0lo, bt0, bufA, NV, HIDD, CDIM);
        }

        // CSR
        k_zero_csr<<<(NV + 255) / 256, 256, 0, s>>>(degE, degV);
        k_count<<<EB, 256, 0, s>>>(vi, ei, degV, degE);
        k_scan<<<1, 1024, 0, s>>>(degE, eoff, ecur, ME);
        k_scan<<<1, 1024, 0, s>>>(degV, voff, vcur, NV);
        k_fill<<<EB, 256, 0, s>>>(vi, ei, ecur, vcur, elist, vlist);

        // layer 1 aggregation (elu), emit bf16 hi/lo for layer-2 GEMM
        k_v2e<HIDD, true><<<ME, HIDD / 4, 0, s>>>(bufA, we0, Y, alpha, nullptr, eoff, elist);
        k_vstats<<<(NV + 255) / 256, 256, 0, s>>>(alpha, voff, vlist, vm, vwinv);
        k_e2v<HIDD, true><<<NV, HIDD / 4, 0, s>>>(Y, nullptr, Acthi, Actlo,
                                                  voff, vlist, alpha, vm, vwinv);

        // layer 2 (HID -> C, no elu)
        {
            dim3 g(CDIM / 128, (NV + 127) / 128);
            k_mma_gemm<true><<<g, 256, GSMEM3, s>>>(Acthi, Actlo, Wt1hi, Wt1lo, bt1, bufC, NV, CDIM, HIDD);
        }
        k_v2e<CDIM, true><<<ME, CDIM / 4, 0, s>>>(bufC, we1, Y, alpha, nullptr, eoff, elist);
        k_vstats<<<(NV + 255) / 256, 256, 0, s>>>(alpha, voff, vlist, vm, vwinv);
        k_e2v<CDIM, false><<<NV, CDIM / 4, 0, s>>>(Y, bufD, Acthi, nullptr,
                                                   voff, vlist, alpha, vm, vwinv);

        // y = v2e_mean(h): fp32 + bf16 hi (into Actlo region)
        k_v2e<CDIM, false><<<ME, CDIM / 4, 0, s>>>(bufD, nullptr, ybuf, alpha, Actlo, eoff, elist);

        // gated attention on h (20000 rows), single-pass bf16
        {
            dim3 g(512 / 128, (NV + 127) / 128);
            k_mma_gemm<false><<<g, 256, GSMEM1, s>>>(Acthi, nbf, Wabhi, nbf,
                                                     (const float*)nullptr, bufA, NV, 512, CDIM);
        }
        k_logits<<<NV, 256, 0, s>>>(bufA, ba, bb, Wc, bc, logits);
        k_attn_init<<<4, 256, 0, s>>>(gvec, menc, S);
        k_maxred<<<40, 256, 0, s>>>(logits, NV, menc);
        k_sumexp<<<40, 256, 0, s>>>(logits, NV, menc, S);
        {
            dim3 g(CDIM / 256, 125);
            k_wsum<<<g, 256, 0, s>>>(bufD, logits, NV, menc, S, gvec);
        }
        k_gemv<<<128, 256, 0, s>>>(gvec, Wout, bout, gout, CDIM, CDIM);
        k_ln<<<1, 256, 0, s>>>(gout, gbn, bbn, gcat + (size_t)b * CDIM, CDIM);

        // gated attention on y (5000 rows), single-pass bf16
        {
            dim3 g(512 / 128, (ME + 127) / 128);
            k_mma_gemm<false><<<g, 256, GSMEM1, s>>>(Actlo, nbf, Wabhi, nbf,
                                                     (const float*)nullptr, ABy, ME, 512, CDIM);
        }
        k_logits<<<ME, 256, 0, s>>>(ABy, ba, bb, Wc, bc, logits);
        k_attn_init<<<4, 256, 0, s>>>(gvec, menc, S);
        k_maxred<<<20, 256, 0, s>>>(logits, ME, menc);
        k_sumexp<<<20, 256, 0, s>>>(logits, ME, menc, S);
        {
            dim3 g(CDIM / 256, 125);
            k_wsum<<<g, 256, 0, s>>>(ybuf, logits, ME, menc, S, gvec);
        }
        k_gemv<<<128, 256, 0, s>>>(gvec, Wout, bout, gout, CDIM, CDIM);
        k_ln<<<1, 256, 0, s>>>(gout, gbn, bbn, gcat + (size_t)(3 + b) * CDIM, CDIM);
    }

    // join branch streams back into the capture stream
    for (int b = 0; b < NB; ++b) {
        cudaEventRecord(evD[b], st[b]);
        cudaStreamWaitEvent(0, evD[b], 0);
    }

    // final: LN(concat) @ Wf^T + bf
    k_ln<<<1, 256>>>(gcat, gbn2, bbn2, gcatn, 6 * CDIM);
    k_gemv<<<2, 256>>>(gcatn, Wf, bf, (float*)d_out, 10, 6 * CDIM);
}